// round 5
// baseline (speedup 1.0000x reference)
#include <cuda_runtime.h>
#include <cuda_bf16.h>
#include <mma.h>
using namespace nvcuda;

#define NMAX 50000
#define EMAX 500000
#define BM 128
#define BN 128
#define BK 32

// ---------------- device scratch (static allocations, allowed) --------------
__device__ float g_qkv [(size_t)NMAX * 384];   // Q | K | V per row (stride 384)
__device__ float g_agg [(size_t)NMAX * 128];   // attention output
__device__ float g_buf1[(size_t)NMAX * 128];   // h1 = x + agg@WO + bO (pre-BN1)
__device__ float g_buf2[(size_t)NMAX * 256];   // FFN hidden
__device__ float g_wpack[128 * 384];           // WQ|WK|WV packed [k][3*128]
__device__ int   g_cnt   [NMAX];
__device__ int   g_rp    [NMAX + 1];
__device__ int   g_cursor[NMAX];
__device__ int   g_srcs  [EMAX];
__device__ int   g_bsum  [256];
__device__ int   g_is64;
__device__ float g_red[512];   // [sum1|sq1|sum2|sq2] x128
__device__ float g_aff[512];   // [sc1|sh1|sc2|sh2]   x128

__device__ __forceinline__ float* bufptr(int id) {
    switch (id) {
        case 0: return g_qkv;
        case 1: return g_agg;
        case 2: return g_buf1;
        case 3: return g_buf2;
        case 4: return g_wpack;
    }
    return 0;
}

__device__ __forceinline__ int edge_at(const void* ei, size_t idx) {
    if (g_is64) return (int)((const long long*)ei)[idx];
    return ((const int*)ei)[idx];
}

// ---------------------------- small kernels ---------------------------------
__global__ void k_detect(const void* ei, int e) {
    if (threadIdx.x == 0) {
        const long long* p = (const long long*)ei;
        int m = e < 256 ? e : 256;
        int ok = 1;
        for (int i = 0; i < m; i++) {
            long long v = p[i];
            if (v < 0 || v >= NMAX) { ok = 0; break; }
        }
        g_is64 = ok;
    }
}

__global__ void k_pack(const float* __restrict__ WQ, const float* __restrict__ WK,
                       const float* __restrict__ WV) {
    int i = blockIdx.x * 256 + threadIdx.x;
    if (i < 128 * 128) {
        int k = i >> 7, m = i & 127;
        g_wpack[k * 384 + m]       = WQ[i];
        g_wpack[k * 384 + 128 + m] = WK[i];
        g_wpack[k * 384 + 256 + m] = WV[i];
    }
}

__global__ void k_zero(int n) {
    int i = blockIdx.x * blockDim.x + threadIdx.x;
    if (i < n)   g_cnt[i] = 0;
    if (i < 512) g_red[i] = 0.f;
}

__global__ void k_hist(const void* ei, int e) {
    int i = blockIdx.x * blockDim.x + threadIdx.x;
    if (i < e) {
        int d = edge_at(ei, (size_t)e + i);
        atomicAdd(&g_cnt[d], 1);
    }
}

__global__ void k_scan1(int n) {
    __shared__ int sh[1024];
    int t = threadIdx.x;
    int idx = blockIdx.x * 1024 + t;
    int v = (idx < n) ? g_cnt[idx] : 0;
    sh[t] = v;
    __syncthreads();
    for (int off = 1; off < 1024; off <<= 1) {
        int add = (t >= off) ? sh[t - off] : 0;
        __syncthreads();
        sh[t] += add;
        __syncthreads();
    }
    if (idx < n) g_rp[idx] = sh[t] - v;     // exclusive
    if (t == 1023) g_bsum[blockIdx.x] = sh[1023];
}

__global__ void k_scan2(int nb) {
    if (threadIdx.x == 0) {
        int run = 0;
        for (int i = 0; i < nb; i++) { int c = g_bsum[i]; g_bsum[i] = run; run += c; }
    }
}

__global__ void k_scan3(int n, int e) {
    int idx = blockIdx.x * 1024 + threadIdx.x;
    if (idx < n) {
        int v = g_rp[idx] + g_bsum[blockIdx.x];
        g_rp[idx] = v;
        g_cursor[idx] = v;
    }
    if (idx == 0) g_rp[n] = e;
}

__global__ void k_scatter(const void* ei, int e) {
    int i = blockIdx.x * blockDim.x + threadIdx.x;
    if (i < e) {
        int d = edge_at(ei, (size_t)e + i);
        int s = edge_at(ei, (size_t)i);
        int p = atomicAdd(&g_cursor[d], 1);
        g_srcs[p] = s;
    }
}

// ---------------- attention: one warp per destination node ------------------
// exp(score) directly (scores clipped to [-5,5]) == max-subtracted softmax.
// Unrolled x2 for memory-level parallelism on the L2 gather.
__global__ void k_attn(int n) {
    int warp = (blockIdx.x * blockDim.x + threadIdx.x) >> 5;
    int lane = threadIdx.x & 31;
    if (warp >= n) return;

    float4 q = *(const float4*)(g_qkv + (size_t)warp * 384 + lane * 4);

    float ax = 0.f, ay = 0.f, az = 0.f, aw = 0.f, se = 0.f;
    int beg = g_rp[warp], end = g_rp[warp + 1];
    int p = beg;
    for (; p + 1 < end; p += 2) {
        int j0 = g_srcs[p];
        int j1 = g_srcs[p + 1];
        const float* b0 = g_qkv + (size_t)j0 * 384;
        const float* b1 = g_qkv + (size_t)j1 * 384;
        float4 k0 = *(const float4*)(b0 + 128 + lane * 4);
        float4 v0 = *(const float4*)(b0 + 256 + lane * 4);
        float4 k1 = *(const float4*)(b1 + 128 + lane * 4);
        float4 v1 = *(const float4*)(b1 + 256 + lane * 4);

        float s0 = q.x * k0.x + q.y * k0.y + q.z * k0.z + q.w * k0.w;
        float s1 = q.x * k1.x + q.y * k1.y + q.z * k1.z + q.w * k1.w;
        s0 += __shfl_xor_sync(0xffffffffu, s0, 1);
        s1 += __shfl_xor_sync(0xffffffffu, s1, 1);
        s0 += __shfl_xor_sync(0xffffffffu, s0, 2);
        s1 += __shfl_xor_sync(0xffffffffu, s1, 2);
        s0 = fminf(fmaxf(s0 * 0.25f, -5.f), 5.f);
        s1 = fminf(fmaxf(s1 * 0.25f, -5.f), 5.f);
        float e0 = __expf(s0);
        float e1 = __expf(s1);
        ax += e0 * v0.x + e1 * v1.x;
        ay += e0 * v0.y + e1 * v1.y;
        az += e0 * v0.z + e1 * v1.z;
        aw += e0 * v0.w + e1 * v1.w;
        se += e0 + e1;
    }
    if (p < end) {
        int j = g_srcs[p];
        const float* base = g_qkv + (size_t)j * 384;
        float4 kv = *(const float4*)(base + 128 + lane * 4);
        float4 vv = *(const float4*)(base + 256 + lane * 4);
        float s = q.x * kv.x + q.y * kv.y + q.z * kv.z + q.w * kv.w;
        s += __shfl_xor_sync(0xffffffffu, s, 1);
        s += __shfl_xor_sync(0xffffffffu, s, 2);
        s = fminf(fmaxf(s * 0.25f, -5.f), 5.f);
        float e = __expf(s);
        ax += e * vv.x; ay += e * vv.y; az += e * vv.z; aw += e * vv.w;
        se += e;
    }
    float inv = 1.0f / (se + 1e-16f);
    float4 o = make_float4(ax * inv, ay * inv, az * inv, aw * inv);
    *(float4*)(g_agg + (size_t)warp * 128 + lane * 4) = o;
}

// --------------- tensor-core GEMM: bf16 3-term split, pipelined --------------
// C[:, cols] = op( A' @ W + bias + resid' ), BK=32, register prefetch of the
// next k-tile overlaps global latency with the mma stage.
__global__ __launch_bounds__(256) void tgemm(
    const float* __restrict__ Aext, int Aid,
    const float* __restrict__ W, int Wid, int Wld,
    float* __restrict__ Cext, int Cid,
    int nrows, int K, int ldc,
    const float* __restrict__ bias,
    const float* __restrict__ Rext, int rid, int hasResid, int ldres,
    int ascSlot, int rscSlot, int doRelu)
{
    __shared__ __nv_bfloat16 AsH[BM][BK + 8];   // 128 x 40
    __shared__ __nv_bfloat16 AsL[BM][BK + 8];
    __shared__ __nv_bfloat16 WsH[BK][BN + 8];   // 32 x 136
    __shared__ __nv_bfloat16 WsL[BK][BN + 8];
    __shared__ float Cs[8][16][16];             // per-warp epilogue scratch

    const float* A  = (Aid >= 0) ? bufptr(Aid) : Aext;
    const float* Wp = (Wid >= 0) ? bufptr(Wid) : W;
    float*       C  = (Cid >= 0) ? bufptr(Cid) : Cext;
    const float* resid = hasResid ? ((rid >= 0) ? bufptr(rid) : Rext) : 0;

    int tid  = threadIdx.x;
    int warp = tid >> 5;
    int lane = tid & 31;
    int rowBase = blockIdx.x * BM;
    int colBase = blockIdx.y * BN;

    int wRow = (warp >> 2) * 64;        // warps 2 (row) x 4 (col); tile 64x32
    int wCol = (warp & 3) * 32;

    wmma::fragment<wmma::accumulator, 16, 16, 16, float> acc[4][2];
#pragma unroll
    for (int i = 0; i < 4; i++)
#pragma unroll
        for (int j = 0; j < 2; j++) wmma::fill_fragment(acc[i][j], 0.f);

    const float* asc = g_aff + (ascSlot >= 0 ? ascSlot : 0) * 128;
    const float* ash = asc + 128;

    // per-thread load coords: 4 float4 each for A and W per k-tile
    int aR[4], aC[4], wR[4], wC[4];
#pragma unroll
    for (int u = 0; u < 4; u++) {
        int f4 = tid * 4 + u;           // 0..1023
        aR[u] = f4 >> 3;                // 0..127
        aC[u] = (f4 & 7) * 4;           // 0..28
        wR[u] = f4 >> 5;                // 0..31
        wC[u] = (f4 & 31) * 4;          // 0..124
    }

    float4 pa[4], pw[4];
    // preload k-tile 0
#pragma unroll
    for (int u = 0; u < 4; u++) {
        int arow = rowBase + aR[u];
        pa[u] = make_float4(0.f, 0.f, 0.f, 0.f);
        if (arow < nrows)
            pa[u] = *(const float4*)(A + (size_t)arow * K + aC[u]);
        pw[u] = *(const float4*)(Wp + (size_t)wR[u] * Wld + colBase + wC[u]);
    }

    for (int k0 = 0; k0 < K; k0 += BK) {
        // convert current regs -> smem (hi/lo split, BN-affine on A)
#pragma unroll
        for (int u = 0; u < 4; u++) {
            float vv[4] = {pa[u].x, pa[u].y, pa[u].z, pa[u].w};
            if (ascSlot >= 0) {
                int kk = k0 + aC[u];
#pragma unroll
                for (int j = 0; j < 4; j++) vv[j] = vv[j] * asc[kk + j] + ash[kk + j];
            }
#pragma unroll
            for (int j = 0; j < 4; j++) {
                __nv_bfloat16 h = __float2bfloat16(vv[j]);
                AsH[aR[u]][aC[u] + j] = h;
                AsL[aR[u]][aC[u] + j] = __float2bfloat16(vv[j] - __bfloat162float(h));
            }
            float ww[4] = {pw[u].x, pw[u].y, pw[u].z, pw[u].w};
#pragma unroll
            for (int j = 0; j < 4; j++) {
                __nv_bfloat16 h = __float2bfloat16(ww[j]);
                WsH[wR[u]][wC[u] + j] = h;
                WsL[wR[u]][wC[u] + j] = __float2bfloat16(ww[j] - __bfloat162float(h));
            }
        }
        __syncthreads();

        // prefetch next k-tile (overlaps with mma below)
        int kn = k0 + BK;
        if (kn < K) {
#pragma unroll
            for (int u = 0; u < 4; u++) {
                int arow = rowBase + aR[u];
                pa[u] = make_float4(0.f, 0.f, 0.f, 0.f);
                if (arow < nrows)
                    pa[u] = *(const float4*)(A + (size_t)arow * K + kn + aC[u]);
                pw[u] = *(const float4*)(Wp + (size_t)(kn + wR[u]) * Wld + colBase + wC[u]);
            }
        }

#pragma unroll
        for (int kk = 0; kk < BK; kk += 16) {
            wmma::fragment<wmma::matrix_a, 16, 16, 16, __nv_bfloat16, wmma::row_major> aH[4], aL[4];
            wmma::fragment<wmma::matrix_b, 16, 16, 16, __nv_bfloat16, wmma::row_major> bH[2], bL[2];
#pragma unroll
            for (int mi = 0; mi < 4; mi++) {
                wmma::load_matrix_sync(aH[mi], &AsH[wRow + mi * 16][kk], BK + 8);
                wmma::load_matrix_sync(aL[mi], &AsL[wRow + mi * 16][kk], BK + 8);
            }
#pragma unroll
            for (int ni = 0; ni < 2; ni++) {
                wmma::load_matrix_sync(bH[ni], &WsH[kk][wCol + ni * 16], BN + 8);
                wmma::load_matrix_sync(bL[ni], &WsL[kk][wCol + ni * 16], BN + 8);
            }
#pragma unroll
            for (int mi = 0; mi < 4; mi++)
#pragma unroll
                for (int ni = 0; ni < 2; ni++) {
                    wmma::mma_sync(acc[mi][ni], aH[mi], bL[ni], acc[mi][ni]);
                    wmma::mma_sync(acc[mi][ni], aL[mi], bH[ni], acc[mi][ni]);
                    wmma::mma_sync(acc[mi][ni], aH[mi], bH[ni], acc[mi][ni]);
                }
        }
        __syncthreads();
    }

    // fused epilogue via per-warp smem scratch
#pragma unroll
    for (int mi = 0; mi < 4; mi++)
#pragma unroll
        for (int ni = 0; ni < 2; ni++) {
            wmma::store_matrix_sync(&Cs[warp][0][0], acc[mi][ni], 16, wmma::mem_row_major);
            __syncwarp();
            int r16 = lane >> 1;
            int c0  = (lane & 1) * 8;
            int row = rowBase + wRow + mi * 16 + r16;
            if (row < nrows) {
                int colb = colBase + wCol + ni * 16 + c0;
#pragma unroll
                for (int j = 0; j < 8; j++) {
                    int c = colb + j;
                    float v = Cs[warp][r16][c0 + j];
                    if (bias) v += bias[c];
                    if (resid) {
                        float rr = resid[(size_t)row * ldres + c];
                        if (rscSlot >= 0)
                            rr = rr * g_aff[rscSlot * 128 + c] + g_aff[(rscSlot + 1) * 128 + c];
                        v += rr;
                    }
                    if (doRelu) v = fmaxf(v, 0.f);
                    C[(size_t)row * ldc + c] = v;
                }
            }
            __syncwarp();
        }
}

// ------------------------- batchnorm stats / apply ---------------------------
__global__ void k_stats(int bid, int n, int slot) {
    const float* h = bufptr(bid);
    int c = threadIdx.x;
    float s = 0.f, s2 = 0.f;
    for (int r = blockIdx.x; r < n; r += gridDim.x) {
        float v = h[(size_t)r * 128 + c];
        s += v; s2 += v * v;
    }
    atomicAdd(&g_red[slot * 128 + c], s);
    atomicAdd(&g_red[(slot + 1) * 128 + c], s2);
}

__global__ void k_stats_ext(const float* __restrict__ h, int n, int slot) {
    int c = threadIdx.x;
    float s = 0.f, s2 = 0.f;
    for (int r = blockIdx.x; r < n; r += gridDim.x) {
        float v = h[(size_t)r * 128 + c];
        s += v; s2 += v * v;
    }
    atomicAdd(&g_red[slot * 128 + c], s);
    atomicAdd(&g_red[(slot + 1) * 128 + c], s2);
}

__global__ void k_fin(int slot, const float* __restrict__ gam,
                      const float* __restrict__ bet, int aslot, int n) {
    int c = threadIdx.x;
    float mean = g_red[slot * 128 + c] / (float)n;
    float var  = g_red[(slot + 1) * 128 + c] / (float)n - mean * mean;
    float inv  = rsqrtf(var + 1e-5f);
    float sc   = gam[c] * inv;
    g_aff[aslot * 128 + c]       = sc;
    g_aff[(aslot + 1) * 128 + c] = bet[c] - mean * sc;
}

__global__ void k_apply(float* __restrict__ out, int total) {
    int i = blockIdx.x * blockDim.x + threadIdx.x;
    if (i < total) {
        int c = i & 127;
        out[i] = out[i] * g_aff[256 + c] + g_aff[384 + c];
    }
}

// ------------------------------- launcher ------------------------------------
extern "C" void kernel_launch(void* const* d_in, const int* in_sizes, int n_in,
                              void* d_out, int out_size) {
    const float* x   = (const float*)d_in[0];
    const void*  ei  = d_in[1];
    const float* WQ  = (const float*)d_in[2];
    const float* WK  = (const float*)d_in[3];
    const float* WV  = (const float*)d_in[4];
    const float* WO  = (const float*)d_in[5];
    const float* bO  = (const float*)d_in[6];
    const float* W1  = (const float*)d_in[7];
    const float* b1  = (const float*)d_in[8];
    const float* W2  = (const float*)d_in[9];
    const float* b2  = (const float*)d_in[10];
    const float* g1v = (const float*)d_in[11];
    const float* be1 = (const float*)d_in[12];
    const float* g2v = (const float*)d_in[13];
    const float* be2 = (const float*)d_in[14];

    int n = in_sizes[0] / 128;
    int e = in_sizes[1] / 2;
    float* out = (float*)d_out;

    int nb = (n + 1023) / 1024;

    // CSR build (by destination) + weight packing
    k_detect <<<1, 32>>>(ei, e);
    k_pack   <<<64, 256>>>(WQ, WK, WV);
    k_zero   <<<(n + 255) / 256, 256>>>(n);
    k_hist   <<<(e + 255) / 256, 256>>>(ei, e);
    k_scan1  <<<nb, 1024>>>(n);
    k_scan2  <<<1, 32>>>(nb);
    k_scan3  <<<nb, 1024>>>(n, e);
    k_scatter<<<(e + 255) / 256, 256>>>(ei, e);

    dim3 gQKV((n + 127) / 128, 3);
    dim3 g1((n + 127) / 128, 1);
    dim3 g2((n + 127) / 128, 2);

    // QKV: x @ [WQ|WK|WV] -> g_qkv [N,384]  (Wid=4 -> g_wpack, Wld=384)
    tgemm<<<gQKV, 256>>>(x, -1, 0, 4, 384, 0, 0, n, 128, 384,
                         0, 0, -1, 0, 0, -1, -1, 0);

    // segment softmax attention, warp per node
    k_attn<<<(n + 7) / 8, 256>>>(n);

    // h1 = agg @ WO + bO + x
    tgemm<<<g1, 256>>>(0, 1, WO, -1, 128, 0, 2, n, 128, 128,
                       bO, x, -1, 1, 128, -1, -1, 0);

    // BN1 stats -> (scale1, shift1) in g_aff slots 0/1, fused downstream
    k_stats<<<512, 128>>>(2, n, 0);
    k_fin  <<<1, 128>>>(0, g1v, be1, 0, n);

    // hidden = relu( BN1(h1) @ W1 + b1 )
    tgemm<<<g2, 256>>>(0, 2, W1, -1, 256, 0, 3, n, 128, 256,
                       b1, 0, -1, 0, 0, 0, -1, 1);

    // h3 = hidden @ W2 + b2 + BN1(h1)  -> d_out (pre-BN2)
    tgemm<<<g1, 256>>>(0, 3, W2, -1, 128, out, -1, n, 256, 128,
                       b2, 0, 2, 1, 128, -1, 0, 0);

    // BN2 stats -> apply in place on d_out
    k_stats_ext<<<512, 128>>>(out, n, 2);
    k_fin      <<<1, 128>>>(2, g2v, be2, 2, n);
    k_apply    <<<(n * 128 + 255) / 256, 256>>>(out, n * 128);
}

// round 6
// speedup vs baseline: 1.2105x; 1.2105x over previous
#include <cuda_runtime.h>
#include <cuda_bf16.h>
#include <mma.h>
using namespace nvcuda;

#define NMAX 50000
#define EMAX 500000
#define BM 128
#define BN 128
#define BK 16

// ---------------- device scratch (static allocations, allowed) --------------
__device__ float g_qkv [(size_t)NMAX * 384];   // Q | K | V per row (stride 384)
__device__ float g_agg [(size_t)NMAX * 128];   // attention output
__device__ float g_buf1[(size_t)NMAX * 128];   // h1 = x + agg@WO + bO (pre-BN1)
__device__ float g_buf2[(size_t)NMAX * 256];   // FFN hidden
__device__ float g_wpack[128 * 384];           // WQ|WK|WV packed [k][3*128]
__device__ int   g_cnt   [NMAX];
__device__ int   g_rp    [NMAX + 1];
__device__ int   g_cursor[NMAX];
__device__ int   g_srcs  [EMAX];
__device__ int   g_bsum  [256];
__device__ int   g_is64;
__device__ float g_red[512];   // [sum1|sq1|sum2|sq2] x128
__device__ float g_aff[512];   // [sc1|sh1|sc2|sh2]   x128

__device__ __forceinline__ float* bufptr(int id) {
    switch (id) {
        case 0: return g_qkv;
        case 1: return g_agg;
        case 2: return g_buf1;
        case 3: return g_buf2;
        case 4: return g_wpack;
    }
    return 0;
}

__device__ __forceinline__ int edge_at(const void* ei, size_t idx) {
    if (g_is64) return (int)((const long long*)ei)[idx];
    return ((const int*)ei)[idx];
}

// ---------------------------- small kernels ---------------------------------
__global__ void k_detect(const void* ei, int e) {
    if (threadIdx.x == 0) {
        const long long* p = (const long long*)ei;
        int m = e < 256 ? e : 256;
        int ok = 1;
        for (int i = 0; i < m; i++) {
            long long v = p[i];
            if (v < 0 || v >= NMAX) { ok = 0; break; }
        }
        g_is64 = ok;
    }
}

__global__ void k_pack(const float* __restrict__ WQ, const float* __restrict__ WK,
                       const float* __restrict__ WV) {
    int i = blockIdx.x * 256 + threadIdx.x;
    if (i < 128 * 128) {
        int k = i >> 7, m = i & 127;
        g_wpack[k * 384 + m]       = WQ[i];
        g_wpack[k * 384 + 128 + m] = WK[i];
        g_wpack[k * 384 + 256 + m] = WV[i];
    }
}

__global__ void k_zero(int n) {
    int i = blockIdx.x * blockDim.x + threadIdx.x;
    if (i < n)   g_cnt[i] = 0;
    if (i < 512) g_red[i] = 0.f;
}

__global__ void k_hist(const void* ei, int e) {
    int i = blockIdx.x * blockDim.x + threadIdx.x;
    if (i < e) {
        int d = edge_at(ei, (size_t)e + i);
        atomicAdd(&g_cnt[d], 1);
    }
}

__global__ void k_scan1(int n) {
    __shared__ int sh[1024];
    int t = threadIdx.x;
    int idx = blockIdx.x * 1024 + t;
    int v = (idx < n) ? g_cnt[idx] : 0;
    sh[t] = v;
    __syncthreads();
    for (int off = 1; off < 1024; off <<= 1) {
        int add = (t >= off) ? sh[t - off] : 0;
        __syncthreads();
        sh[t] += add;
        __syncthreads();
    }
    if (idx < n) g_rp[idx] = sh[t] - v;     // exclusive
    if (t == 1023) g_bsum[blockIdx.x] = sh[1023];
}

__global__ void k_scan2(int nb) {
    if (threadIdx.x == 0) {
        int run = 0;
        for (int i = 0; i < nb; i++) { int c = g_bsum[i]; g_bsum[i] = run; run += c; }
    }
}

__global__ void k_scan3(int n, int e) {
    int idx = blockIdx.x * 1024 + threadIdx.x;
    if (idx < n) {
        int v = g_rp[idx] + g_bsum[blockIdx.x];
        g_rp[idx] = v;
        g_cursor[idx] = v;
    }
    if (idx == 0) g_rp[n] = e;
}

__global__ void k_scatter(const void* ei, int e) {
    int i = blockIdx.x * blockDim.x + threadIdx.x;
    if (i < e) {
        int d = edge_at(ei, (size_t)e + i);
        int s = edge_at(ei, (size_t)i);
        int p = atomicAdd(&g_cursor[d], 1);
        g_srcs[p] = s;
    }
}

// ---------------- attention: one warp per destination node ------------------
// exp(score) directly (scores clipped to [-5,5]) == max-subtracted softmax.
__global__ void k_attn(int n) {
    int warp = (blockIdx.x * blockDim.x + threadIdx.x) >> 5;
    int lane = threadIdx.x & 31;
    if (warp >= n) return;

    float4 q = *(const float4*)(g_qkv + (size_t)warp * 384 + lane * 4);

    float ax = 0.f, ay = 0.f, az = 0.f, aw = 0.f, se = 0.f;
    int beg = g_rp[warp], end = g_rp[warp + 1];
    int p = beg;
    for (; p + 1 < end; p += 2) {
        int j0 = g_srcs[p];
        int j1 = g_srcs[p + 1];
        const float* b0 = g_qkv + (size_t)j0 * 384;
        const float* b1 = g_qkv + (size_t)j1 * 384;
        float4 k0 = *(const float4*)(b0 + 128 + lane * 4);
        float4 v0 = *(const float4*)(b0 + 256 + lane * 4);
        float4 k1 = *(const float4*)(b1 + 128 + lane * 4);
        float4 v1 = *(const float4*)(b1 + 256 + lane * 4);

        float s0 = q.x * k0.x + q.y * k0.y + q.z * k0.z + q.w * k0.w;
        float s1 = q.x * k1.x + q.y * k1.y + q.z * k1.z + q.w * k1.w;
        s0 += __shfl_xor_sync(0xffffffffu, s0, 1);
        s1 += __shfl_xor_sync(0xffffffffu, s1, 1);
        s0 += __shfl_xor_sync(0xffffffffu, s0, 2);
        s1 += __shfl_xor_sync(0xffffffffu, s1, 2);
        s0 = fminf(fmaxf(s0 * 0.25f, -5.f), 5.f);
        s1 = fminf(fmaxf(s1 * 0.25f, -5.f), 5.f);
        float e0 = __expf(s0);
        float e1 = __expf(s1);
        ax += e0 * v0.x + e1 * v1.x;
        ay += e0 * v0.y + e1 * v1.y;
        az += e0 * v0.z + e1 * v1.z;
        aw += e0 * v0.w + e1 * v1.w;
        se += e0 + e1;
    }
    if (p < end) {
        int j = g_srcs[p];
        const float* base = g_qkv + (size_t)j * 384;
        float4 kv = *(const float4*)(base + 128 + lane * 4);
        float4 vv = *(const float4*)(base + 256 + lane * 4);
        float s = q.x * kv.x + q.y * kv.y + q.z * kv.z + q.w * kv.w;
        s += __shfl_xor_sync(0xffffffffu, s, 1);
        s += __shfl_xor_sync(0xffffffffu, s, 2);
        s = fminf(fmaxf(s * 0.25f, -5.f), 5.f);
        float e = __expf(s);
        ax += e * vv.x; ay += e * vv.y; az += e * vv.z; aw += e * vv.w;
        se += e;
    }
    float inv = 1.0f / (se + 1e-16f);
    float4 o = make_float4(ax * inv, ay * inv, az * inv, aw * inv);
    *(float4*)(g_agg + (size_t)warp * 128 + lane * 4) = o;
}

// helper: pack 4 bf16 into one 64-bit word
union BF4 { __nv_bfloat16 b[4]; unsigned long long u64; };

// --------------- tensor-core GEMM: bf16 3-term split (m16n16k16) -------------
// C[:, cols] = op( A' @ W + bias + resid' ). Staging uses packed STS.64
// (4 per thread per k-tile instead of 16 scattered STS.16).
__global__ __launch_bounds__(256) void tgemm(
    const float* __restrict__ Aext, int Aid,
    const float* __restrict__ W, int Wid, int Wld,
    float* __restrict__ Cext, int Cid,
    int nrows, int K, int ldc,
    const float* __restrict__ bias,
    const float* __restrict__ Rext, int rid, int hasResid, int ldres,
    int ascSlot, int rscSlot, int doRelu)
{
    __shared__ __align__(16) __nv_bfloat16 AsH[BM][BK + 8];   // 128 x 24
    __shared__ __align__(16) __nv_bfloat16 AsL[BM][BK + 8];
    __shared__ __align__(16) __nv_bfloat16 WsH[BK][BN + 8];   // 16 x 136
    __shared__ __align__(16) __nv_bfloat16 WsL[BK][BN + 8];
    __shared__ float Cs[8][16][16];             // per-warp epilogue scratch

    const float* A  = (Aid >= 0) ? bufptr(Aid) : Aext;
    const float* Wp = (Wid >= 0) ? bufptr(Wid) : W;
    float*       C  = (Cid >= 0) ? bufptr(Cid) : Cext;
    const float* resid = hasResid ? ((rid >= 0) ? bufptr(rid) : Rext) : 0;

    int tid  = threadIdx.x;
    int warp = tid >> 5;
    int lane = tid & 31;
    int rowBase = blockIdx.x * BM;
    int colBase = blockIdx.y * BN;

    int wRow = (warp >> 2) * 64;        // warps 2 (row) x 4 (col); tile 64x32
    int wCol = (warp & 3) * 32;

    wmma::fragment<wmma::accumulator, 16, 16, 16, float> acc[4][2];
#pragma unroll
    for (int i = 0; i < 4; i++)
#pragma unroll
        for (int j = 0; j < 2; j++) wmma::fill_fragment(acc[i][j], 0.f);

    const float* asc = g_aff + (ascSlot >= 0 ? ascSlot : 0) * 128;
    const float* ash = asc + 128;

    for (int k0 = 0; k0 < K; k0 += BK) {
        // stage A tile: 128 x 16 fp32 -> hi/lo bf16, packed 64-bit stores
#pragma unroll
        for (int u = 0; u < 2; u++) {
            int f4 = tid * 2 + u;               // 0..511
            int r  = f4 >> 2;                   // 0..127
            int c4 = (f4 & 3) * 4;              // 0,4,8,12
            float4 av = make_float4(0.f, 0.f, 0.f, 0.f);
            int arow = rowBase + r;
            if (arow < nrows) {
                av = *(const float4*)(A + (size_t)arow * K + k0 + c4);
                if (ascSlot >= 0) {
                    int kk = k0 + c4;
                    av.x = av.x * asc[kk + 0] + ash[kk + 0];
                    av.y = av.y * asc[kk + 1] + ash[kk + 1];
                    av.z = av.z * asc[kk + 2] + ash[kk + 2];
                    av.w = av.w * asc[kk + 3] + ash[kk + 3];
                }
            }
            float vv[4] = {av.x, av.y, av.z, av.w};
            BF4 ph, pl;
#pragma unroll
            for (int j = 0; j < 4; j++) {
                __nv_bfloat16 h = __float2bfloat16(vv[j]);
                ph.b[j] = h;
                pl.b[j] = __float2bfloat16(vv[j] - __bfloat162float(h));
            }
            *(unsigned long long*)(&AsH[r][c4]) = ph.u64;
            *(unsigned long long*)(&AsL[r][c4]) = pl.u64;
        }
        // stage W tile: 16 x 128, packed 64-bit stores
#pragma unroll
        for (int u = 0; u < 2; u++) {
            int f4 = tid * 2 + u;               // 0..511
            int r  = f4 >> 5;                   // 0..15
            int c  = (f4 & 31) * 4;             // 0..124
            float4 wv = *(const float4*)(Wp + (size_t)(k0 + r) * Wld + colBase + c);
            float ww[4] = {wv.x, wv.y, wv.z, wv.w};
            BF4 ph, pl;
#pragma unroll
            for (int j = 0; j < 4; j++) {
                __nv_bfloat16 h = __float2bfloat16(ww[j]);
                ph.b[j] = h;
                pl.b[j] = __float2bfloat16(ww[j] - __bfloat162float(h));
            }
            *(unsigned long long*)(&WsH[r][c]) = ph.u64;
            *(unsigned long long*)(&WsL[r][c]) = pl.u64;
        }
        __syncthreads();

        wmma::fragment<wmma::matrix_a, 16, 16, 16, __nv_bfloat16, wmma::row_major> aH[4], aL[4];
        wmma::fragment<wmma::matrix_b, 16, 16, 16, __nv_bfloat16, wmma::row_major> bH[2], bL[2];
#pragma unroll
        for (int mi = 0; mi < 4; mi++) {
            wmma::load_matrix_sync(aH[mi], &AsH[wRow + mi * 16][0], BK + 8);
            wmma::load_matrix_sync(aL[mi], &AsL[wRow + mi * 16][0], BK + 8);
        }
#pragma unroll
        for (int ni = 0; ni < 2; ni++) {
            wmma::load_matrix_sync(bH[ni], &WsH[0][wCol + ni * 16], BN + 8);
            wmma::load_matrix_sync(bL[ni], &WsL[0][wCol + ni * 16], BN + 8);
        }
#pragma unroll
        for (int mi = 0; mi < 4; mi++)
#pragma unroll
            for (int ni = 0; ni < 2; ni++) {
                wmma::mma_sync(acc[mi][ni], aH[mi], bL[ni], acc[mi][ni]);
                wmma::mma_sync(acc[mi][ni], aL[mi], bH[ni], acc[mi][ni]);
                wmma::mma_sync(acc[mi][ni], aH[mi], bH[ni], acc[mi][ni]);
            }
        __syncthreads();
    }

    // fused epilogue via per-warp smem scratch
#pragma unroll
    for (int mi = 0; mi < 4; mi++)
#pragma unroll
        for (int ni = 0; ni < 2; ni++) {
            wmma::store_matrix_sync(&Cs[warp][0][0], acc[mi][ni], 16, wmma::mem_row_major);
            __syncwarp();
            int r16 = lane >> 1;
            int c0  = (lane & 1) * 8;
            int row = rowBase + wRow + mi * 16 + r16;
            if (row < nrows) {
                int colb = colBase + wCol + ni * 16 + c0;
#pragma unroll
                for (int j = 0; j < 8; j++) {
                    int c = colb + j;
                    float v = Cs[warp][r16][c0 + j];
                    if (bias) v += bias[c];
                    if (resid) {
                        float rr = resid[(size_t)row * ldres + c];
                        if (rscSlot >= 0)
                            rr = rr * g_aff[rscSlot * 128 + c] + g_aff[(rscSlot + 1) * 128 + c];
                        v += rr;
                    }
                    if (doRelu) v = fmaxf(v, 0.f);
                    C[(size_t)row * ldc + c] = v;
                }
            }
            __syncwarp();
        }
}

// ------------------------- batchnorm stats / apply ---------------------------
__global__ void k_stats(int bid, int n, int slot) {
    const float* h = bufptr(bid);
    int c = threadIdx.x;
    float s = 0.f, s2 = 0.f;
    for (int r = blockIdx.x; r < n; r += gridDim.x) {
        float v = h[(size_t)r * 128 + c];
        s += v; s2 += v * v;
    }
    atomicAdd(&g_red[slot * 128 + c], s);
    atomicAdd(&g_red[(slot + 1) * 128 + c], s2);
}

__global__ void k_stats_ext(const float* __restrict__ h, int n, int slot) {
    int c = threadIdx.x;
    float s = 0.f, s2 = 0.f;
    for (int r = blockIdx.x; r < n; r += gridDim.x) {
        float v = h[(size_t)r * 128 + c];
        s += v; s2 += v * v;
    }
    atomicAdd(&g_red[slot * 128 + c], s);
    atomicAdd(&g_red[(slot + 1) * 128 + c], s2);
}

__global__ void k_fin(int slot, const float* __restrict__ gam,
                      const float* __restrict__ bet, int aslot, int n) {
    int c = threadIdx.x;
    float mean = g_red[slot * 128 + c] / (float)n;
    float var  = g_red[(slot + 1) * 128 + c] / (float)n - mean * mean;
    float inv  = rsqrtf(var + 1e-5f);
    float sc   = gam[c] * inv;
    g_aff[aslot * 128 + c]       = sc;
    g_aff[(aslot + 1) * 128 + c] = bet[c] - mean * sc;
}

__global__ void k_apply(float* __restrict__ out, int total) {
    int i = blockIdx.x * blockDim.x + threadIdx.x;
    if (i < total) {
        int c = i & 127;
        out[i] = out[i] * g_aff[256 + c] + g_aff[384 + c];
    }
}

// ------------------------------- launcher ------------------------------------
extern "C" void kernel_launch(void* const* d_in, const int* in_sizes, int n_in,
                              void* d_out, int out_size) {
    const float* x   = (const float*)d_in[0];
    const void*  ei  = d_in[1];
    const float* WQ  = (const float*)d_in[2];
    const float* WK  = (const float*)d_in[3];
    const float* WV  = (const float*)d_in[4];
    const float* WO  = (const float*)d_in[5];
    const float* bO  = (const float*)d_in[6];
    const float* W1  = (const float*)d_in[7];
    const float* b1  = (const float*)d_in[8];
    const float* W2  = (const float*)d_in[9];
    const float* b2  = (const float*)d_in[10];
    const float* g1v = (const float*)d_in[11];
    const float* be1 = (const float*)d_in[12];
    const float* g2v = (const float*)d_in[13];
    const float* be2 = (const float*)d_in[14];

    int n = in_sizes[0] / 128;
    int e = in_sizes[1] / 2;
    float* out = (float*)d_out;

    int nb = (n + 1023) / 1024;

    // CSR build (by destination) + weight packing
    k_detect <<<1, 32>>>(ei, e);
    k_pack   <<<64, 256>>>(WQ, WK, WV);
    k_zero   <<<(n + 255) / 256, 256>>>(n);
    k_hist   <<<(e + 255) / 256, 256>>>(ei, e);
    k_scan1  <<<nb, 1024>>>(n);
    k_scan2  <<<1, 32>>>(nb);
    k_scan3  <<<nb, 1024>>>(n, e);
    k_scatter<<<(e + 255) / 256, 256>>>(ei, e);

    dim3 gQKV((n + 127) / 128, 3);
    dim3 g1((n + 127) / 128, 1);
    dim3 g2((n + 127) / 128, 2);

    // QKV: x @ [WQ|WK|WV] -> g_qkv [N,384]  (Wid=4 -> g_wpack, Wld=384)
    tgemm<<<gQKV, 256>>>(x, -1, 0, 4, 384, 0, 0, n, 128, 384,
                         0, 0, -1, 0, 0, -1, -1, 0);

    // segment softmax attention, warp per node
    k_attn<<<(n + 7) / 8, 256>>>(n);

    // h1 = agg @ WO + bO + x
    tgemm<<<g1, 256>>>(0, 1, WO, -1, 128, 0, 2, n, 128, 128,
                       bO, x, -1, 1, 128, -1, -1, 0);

    // BN1 stats -> (scale1, shift1) in g_aff slots 0/1, fused downstream
    k_stats<<<512, 128>>>(2, n, 0);
    k_fin  <<<1, 128>>>(0, g1v, be1, 0, n);

    // hidden = relu( BN1(h1) @ W1 + b1 )
    tgemm<<<g2, 256>>>(0, 2, W1, -1, 256, 0, 3, n, 128, 256,
                       b1, 0, -1, 0, 0, 0, -1, 1);

    // h3 = hidden @ W2 + b2 + BN1(h1)  -> d_out (pre-BN2)
    tgemm<<<g1, 256>>>(0, 3, W2, -1, 128, out, -1, n, 256, 128,
                       b2, 0, 2, 1, 128, -1, 0, 0);

    // BN2 stats -> apply in place on d_out
    k_stats_ext<<<512, 128>>>(out, n, 2);
    k_fin      <<<1, 128>>>(2, g2v, be2, 2, n);
    k_apply    <<<(n * 128 + 255) / 256, 256>>>(out, n * 128);
}

// round 7
// speedup vs baseline: 1.6899x; 1.3960x over previous
#include <cuda_runtime.h>
#include <cuda_bf16.h>
#include <mma.h>
using namespace nvcuda;

#define NMAX 50000
#define EMAX 500000
#define NPAD (NMAX + 128)

typedef unsigned long long u64;
typedef __nv_bfloat16 bf16;

// ---------------- device scratch (static allocations, allowed) --------------
__device__ float g_qkv [(size_t)NMAX * 384];    // Q|K|V fp32 (attention input)
__device__ float g_buf1[(size_t)NMAX * 128];    // h1 fp32 (BN1 stats + residual)
__device__ float g_b1fold[256];                 // b1 + sh1^T W1

__device__ __align__(16) bf16 g_xh  [(size_t)NPAD * 128];
__device__ __align__(16) bf16 g_xl  [(size_t)NPAD * 128];
__device__ __align__(16) bf16 g_aggh[(size_t)NPAD * 128];
__device__ __align__(16) bf16 g_aggl[(size_t)NPAD * 128];
__device__ __align__(16) bf16 g_b1h [(size_t)NPAD * 128];
__device__ __align__(16) bf16 g_b1l [(size_t)NPAD * 128];
__device__ __align__(16) bf16 g_b2h [(size_t)NPAD * 256];
__device__ __align__(16) bf16 g_b2l [(size_t)NPAD * 256];
__device__ __align__(16) bf16 g_wqkvh[128 * 384];
__device__ __align__(16) bf16 g_wqkvl[128 * 384];
__device__ __align__(16) bf16 g_woh [128 * 128];
__device__ __align__(16) bf16 g_wol [128 * 128];
__device__ __align__(16) bf16 g_w1h [128 * 256];
__device__ __align__(16) bf16 g_w1l [128 * 256];
__device__ __align__(16) bf16 g_w2h [256 * 128];
__device__ __align__(16) bf16 g_w2l [256 * 128];

__device__ int   g_cnt   [NMAX];
__device__ int   g_rp    [NMAX + 1];
__device__ int   g_cursor[NMAX];
__device__ int   g_srcs  [EMAX];
__device__ int   g_bsum  [256];
__device__ int   g_is64;
__device__ float g_red[512];
__device__ float g_aff[512];

__device__ __forceinline__ bf16* bfptr(int id) {
    switch (id) {
        case 0:  return g_xh;    case 1:  return g_xl;
        case 2:  return g_aggh;  case 3:  return g_aggl;
        case 4:  return g_b1h;   case 5:  return g_b1l;
        case 6:  return g_b2h;   case 7:  return g_b2l;
        case 8:  return g_wqkvh; case 9:  return g_wqkvl;
        case 10: return g_woh;   case 11: return g_wol;
        case 12: return g_w1h;   case 13: return g_w1l;
        case 14: return g_w2h;   case 15: return g_w2l;
    }
    return 0;
}

__device__ __forceinline__ float* fbptr(int id) {
    switch (id) {
        case 0: return g_qkv;
        case 1: return g_buf1;
        case 2: return g_b1fold;
    }
    return 0;
}

__device__ __forceinline__ int edge_at(const void* ei, size_t idx) {
    if (g_is64) return (int)((const long long*)ei)[idx];
    return ((const int*)ei)[idx];
}

union BF4 { bf16 b[4]; u64 uu; };
union BF8 { bf16 b[8]; uint4 u4; };

__device__ __forceinline__ void cp16(void* smem, const void* gmem) {
    unsigned sa = (unsigned)__cvta_generic_to_shared(smem);
    asm volatile("cp.async.cg.shared.global [%0], [%1], 16;\n" :: "r"(sa), "l"(gmem));
}
#define CP_COMMIT() asm volatile("cp.async.commit_group;\n" ::: "memory")
#define CP_WAIT0()  asm volatile("cp.async.wait_group 0;\n" ::: "memory")

// ---------------------------- small kernels ---------------------------------
__global__ void k_detect(const void* ei, int e) {
    if (threadIdx.x == 0) {
        const long long* p = (const long long*)ei;
        int m = e < 256 ? e : 256;
        int ok = 1;
        for (int i = 0; i < m; i++) {
            long long v = p[i];
            if (v < 0 || v >= NMAX) { ok = 0; break; }
        }
        g_is64 = ok;
    }
}

__global__ void k_split_x(const float* __restrict__ x, int total4) {
    int i = blockIdx.x * blockDim.x + threadIdx.x;
    if (i < total4) {
        float4 v = *(const float4*)(x + i * 4);
        float vv[4] = {v.x, v.y, v.z, v.w};
        BF4 h, l;
#pragma unroll
        for (int j = 0; j < 4; j++) {
            bf16 hh = __float2bfloat16(vv[j]);
            h.b[j] = hh;
            l.b[j] = __float2bfloat16(vv[j] - __bfloat162float(hh));
        }
        *(u64*)(g_xh + i * 4) = h.uu;
        *(u64*)(g_xl + i * 4) = l.uu;
    }
}

__device__ __forceinline__ void splitw(float v, bf16* ph, bf16* pl) {
    bf16 h = __float2bfloat16(v);
    *ph = h;
    *pl = __float2bfloat16(v - __bfloat162float(h));
}

__global__ void k_prepw(const float* __restrict__ WQ, const float* __restrict__ WK,
                        const float* __restrict__ WV, const float* __restrict__ WO,
                        const float* __restrict__ W2) {
    int i = blockIdx.x * 256 + threadIdx.x;
    if (i < 16384) {                        // wqkv pack + split
        int k = i >> 7, m = i & 127;
        splitw(WQ[i], &g_wqkvh[k * 384 + m],       &g_wqkvl[k * 384 + m]);
        splitw(WK[i], &g_wqkvh[k * 384 + 128 + m], &g_wqkvl[k * 384 + 128 + m]);
        splitw(WV[i], &g_wqkvh[k * 384 + 256 + m], &g_wqkvl[k * 384 + 256 + m]);
    } else if (i < 32768) {                 // wo split
        int j = i - 16384;
        splitw(WO[j], &g_woh[j], &g_wol[j]);
    } else if (i < 65536) {                 // w2 split (256x128)
        int j = i - 32768;
        splitw(W2[j], &g_w2h[j], &g_w2l[j]);
    }
}

// w1' = diag(sc1) @ W1, split. Run AFTER BN1 finalize.
__global__ void k_prepw1(const float* __restrict__ W1) {
    int i = blockIdx.x * 256 + threadIdx.x;
    if (i < 128 * 256) {
        int k = i >> 8;
        splitw(g_aff[k] * W1[i], &g_w1h[i], &g_w1l[i]);
    }
}

// b1fold[c] = b1[c] + sum_k sh1[k] * W1[k][c]
__global__ void k_foldb1(const float* __restrict__ W1, const float* __restrict__ b1) {
    int c = threadIdx.x;    // 256 threads
    float s = b1[c];
    for (int k = 0; k < 128; k++) s += g_aff[128 + k] * W1[k * 256 + c];
    g_b1fold[c] = s;
}

__global__ void k_zero(int n) {
    int i = blockIdx.x * blockDim.x + threadIdx.x;
    if (i < n)   g_cnt[i] = 0;
    if (i < 512) g_red[i] = 0.f;
}

__global__ void k_hist(const void* ei, int e) {
    int i = blockIdx.x * blockDim.x + threadIdx.x;
    if (i < e) atomicAdd(&g_cnt[edge_at(ei, (size_t)e + i)], 1);
}

__global__ void k_scan1(int n) {
    __shared__ int sh[1024];
    int t = threadIdx.x;
    int idx = blockIdx.x * 1024 + t;
    int v = (idx < n) ? g_cnt[idx] : 0;
    sh[t] = v;
    __syncthreads();
    for (int off = 1; off < 1024; off <<= 1) {
        int add = (t >= off) ? sh[t - off] : 0;
        __syncthreads();
        sh[t] += add;
        __syncthreads();
    }
    if (idx < n) g_rp[idx] = sh[t] - v;
    if (t == 1023) g_bsum[blockIdx.x] = sh[1023];
}

__global__ void k_scan2(int nb) {
    if (threadIdx.x == 0) {
        int run = 0;
        for (int i = 0; i < nb; i++) { int c = g_bsum[i]; g_bsum[i] = run; run += c; }
    }
}

__global__ void k_scan3(int n, int e) {
    int idx = blockIdx.x * 1024 + threadIdx.x;
    if (idx < n) {
        int v = g_rp[idx] + g_bsum[blockIdx.x];
        g_rp[idx] = v;
        g_cursor[idx] = v;
    }
    if (idx == 0) g_rp[n] = e;
}

__global__ void k_scatter(const void* ei, int e) {
    int i = blockIdx.x * blockDim.x + threadIdx.x;
    if (i < e) {
        int d = edge_at(ei, (size_t)e + i);
        int s = edge_at(ei, (size_t)i);
        int p = atomicAdd(&g_cursor[d], 1);
        g_srcs[p] = s;
    }
}

// ---------------- attention: one warp per destination node ------------------
__global__ void k_attn(int n) {
    int warp = (blockIdx.x * blockDim.x + threadIdx.x) >> 5;
    int lane = threadIdx.x & 31;
    if (warp >= n) return;

    float4 q = *(const float4*)(g_qkv + (size_t)warp * 384 + lane * 4);

    float ax = 0.f, ay = 0.f, az = 0.f, aw = 0.f, se = 0.f;
    int beg = g_rp[warp], end = g_rp[warp + 1];
    int p = beg;
    for (; p + 1 < end; p += 2) {
        int j0 = g_srcs[p];
        int j1 = g_srcs[p + 1];
        const float* b0 = g_qkv + (size_t)j0 * 384;
        const float* b1 = g_qkv + (size_t)j1 * 384;
        float4 k0 = *(const float4*)(b0 + 128 + lane * 4);
        float4 v0 = *(const float4*)(b0 + 256 + lane * 4);
        float4 k1 = *(const float4*)(b1 + 128 + lane * 4);
        float4 v1 = *(const float4*)(b1 + 256 + lane * 4);

        float s0 = q.x * k0.x + q.y * k0.y + q.z * k0.z + q.w * k0.w;
        float s1 = q.x * k1.x + q.y * k1.y + q.z * k1.z + q.w * k1.w;
        s0 += __shfl_xor_sync(0xffffffffu, s0, 1);
        s1 += __shfl_xor_sync(0xffffffffu, s1, 1);
        s0 += __shfl_xor_sync(0xffffffffu, s0, 2);
        s1 += __shfl_xor_sync(0xffffffffu, s1, 2);
        s0 = fminf(fmaxf(s0 * 0.25f, -5.f), 5.f);
        s1 = fminf(fmaxf(s1 * 0.25f, -5.f), 5.f);
        float e0 = __expf(s0);
        float e1 = __expf(s1);
        ax += e0 * v0.x + e1 * v1.x;
        ay += e0 * v0.y + e1 * v1.y;
        az += e0 * v0.z + e1 * v1.z;
        aw += e0 * v0.w + e1 * v1.w;
        se += e0 + e1;
    }
    if (p < end) {
        int j = g_srcs[p];
        const float* base = g_qkv + (size_t)j * 384;
        float4 kv = *(const float4*)(base + 128 + lane * 4);
        float4 vv = *(const float4*)(base + 256 + lane * 4);
        float s = q.x * kv.x + q.y * kv.y + q.z * kv.z + q.w * kv.w;
        s += __shfl_xor_sync(0xffffffffu, s, 1);
        s += __shfl_xor_sync(0xffffffffu, s, 2);
        s = fminf(fmaxf(s * 0.25f, -5.f), 5.f);
        float e = __expf(s);
        ax += e * vv.x; ay += e * vv.y; az += e * vv.z; aw += e * vv.w;
        se += e;
    }
    float inv = 1.0f / (se + 1e-16f);
    float o[4] = {ax * inv, ay * inv, az * inv, aw * inv};
    BF4 oh, ol;
#pragma unroll
    for (int j = 0; j < 4; j++) {
        bf16 h = __float2bfloat16(o[j]);
        oh.b[j] = h;
        ol.b[j] = __float2bfloat16(o[j] - __bfloat162float(h));
    }
    *(u64*)(g_aggh + (size_t)warp * 128 + lane * 4) = oh.uu;
    *(u64*)(g_aggl + (size_t)warp * 128 + lane * 4) = ol.uu;
}

// ------ tensor-core GEMM: bf16 3-term split, cp.async double-buffered -------
// C = op( A @ W + bias + resid' ); A,W pre-split bf16 hi/lo pairs (ids h, h+1).
struct PipeBufs {
    unsigned short AsH[2][128][24];
    unsigned short AsL[2][128][24];
    unsigned short WsH[2][16][136];
    unsigned short WsL[2][16][136];
};
union SmemU {
    PipeBufs p;
    float Cs[8][16][16];
};

__global__ __launch_bounds__(256) void pgemm(
    int AHid, int WHid, int Wld,
    float* Cext, int Cid, int CHid,
    int nrows, int K, int ldc,
    const float* biasExt, int biasId,
    const float* Rext, int rid, int hasResid, int ldres, int rscSlot,
    int doRelu)
{
    __shared__ __align__(16) SmemU sm;

    const bf16* AH = bfptr(AHid);
    const bf16* AL = bfptr(AHid + 1);
    const bf16* WH = bfptr(WHid);
    const bf16* WL = bfptr(WHid + 1);
    float* C = (Cid >= 0) ? fbptr(Cid) : Cext;
    bf16* CH = (CHid >= 0) ? bfptr(CHid) : 0;
    bf16* CL = (CHid >= 0) ? bfptr(CHid + 1) : 0;
    const float* bias = (biasId >= 0) ? fbptr(biasId) : biasExt;
    const float* resid = hasResid ? ((rid >= 0) ? fbptr(rid) : Rext) : 0;

    int tid  = threadIdx.x;
    int warp = tid >> 5;
    int lane = tid & 31;
    int rowBase = blockIdx.x * 128;
    int colBase = blockIdx.y * 128;

    int wRow = (warp >> 2) * 64;
    int wCol = (warp & 3) * 32;

    // cp.async coords: A 128x16 = 256 16B-chunks; W 16x128 = 256 chunks
    int ar = tid >> 1;                 // 0..127
    int ak = (tid & 1) * 8;            // 0 or 8 (bf16 elems)
    int wr = tid >> 4;                 // 0..15
    int wc = (tid & 15) * 8;           // 0..120

    wmma::fragment<wmma::accumulator, 16, 16, 16, float> acc[4][2];
#pragma unroll
    for (int i = 0; i < 4; i++)
#pragma unroll
        for (int j = 0; j < 2; j++) wmma::fill_fragment(acc[i][j], 0.f);

    const size_t aOff = (size_t)(rowBase + ar) * K + ak;

    // prologue: stage 0
    cp16(&sm.p.AsH[0][ar][ak], AH + aOff);
    cp16(&sm.p.AsL[0][ar][ak], AL + aOff);
    cp16(&sm.p.WsH[0][wr][wc], WH + (size_t)wr * Wld + colBase + wc);
    cp16(&sm.p.WsL[0][wr][wc], WL + (size_t)wr * Wld + colBase + wc);
    CP_COMMIT();

    int nIter = K >> 4;
    for (int it = 0; it < nIter; it++) {
        int st = it & 1;
        CP_WAIT0();
        __syncthreads();

        int kn = (it + 1) << 4;
        if (kn < K) {
            int sn = st ^ 1;
            cp16(&sm.p.AsH[sn][ar][ak], AH + aOff + kn);
            cp16(&sm.p.AsL[sn][ar][ak], AL + aOff + kn);
            cp16(&sm.p.WsH[sn][wr][wc], WH + (size_t)(kn + wr) * Wld + colBase + wc);
            cp16(&sm.p.WsL[sn][wr][wc], WL + (size_t)(kn + wr) * Wld + colBase + wc);
            CP_COMMIT();
        }

        wmma::fragment<wmma::matrix_a, 16, 16, 16, bf16, wmma::row_major> aH[4], aL[4];
        wmma::fragment<wmma::matrix_b, 16, 16, 16, bf16, wmma::row_major> bH[2], bL[2];
#pragma unroll
        for (int mi = 0; mi < 4; mi++) {
            wmma::load_matrix_sync(aH[mi], (const bf16*)&sm.p.AsH[st][wRow + mi * 16][0], 24);
            wmma::load_matrix_sync(aL[mi], (const bf16*)&sm.p.AsL[st][wRow + mi * 16][0], 24);
        }
#pragma unroll
        for (int ni = 0; ni < 2; ni++) {
            wmma::load_matrix_sync(bH[ni], (const bf16*)&sm.p.WsH[st][0][wCol + ni * 16], 136);
            wmma::load_matrix_sync(bL[ni], (const bf16*)&sm.p.WsL[st][0][wCol + ni * 16], 136);
        }
#pragma unroll
        for (int mi = 0; mi < 4; mi++)
#pragma unroll
            for (int ni = 0; ni < 2; ni++) {
                wmma::mma_sync(acc[mi][ni], aH[mi], bL[ni], acc[mi][ni]);
                wmma::mma_sync(acc[mi][ni], aL[mi], bH[ni], acc[mi][ni]);
                wmma::mma_sync(acc[mi][ni], aH[mi], bH[ni], acc[mi][ni]);
            }
    }

    __syncthreads();   // before Cs aliases pipeline buffers

    // fused epilogue via per-warp smem scratch
#pragma unroll
    for (int mi = 0; mi < 4; mi++)
#pragma unroll
        for (int ni = 0; ni < 2; ni++) {
            wmma::store_matrix_sync(&sm.Cs[warp][0][0], acc[mi][ni], 16, wmma::mem_row_major);
            __syncwarp();
            int r16 = lane >> 1;
            int c0  = (lane & 1) * 8;
            int row = rowBase + wRow + mi * 16 + r16;
            if (row < nrows) {
                int colb = colBase + wCol + ni * 16 + c0;
                float v[8];
#pragma unroll
                for (int j = 0; j < 8; j++) {
                    v[j] = sm.Cs[warp][r16][c0 + j];
                    if (bias) v[j] += bias[colb + j];
                }
                if (resid) {
                    float4 r0 = *(const float4*)(resid + (size_t)row * ldres + colb);
                    float4 r1 = *(const float4*)(resid + (size_t)row * ldres + colb + 4);
                    float rr[8] = {r0.x, r0.y, r0.z, r0.w, r1.x, r1.y, r1.z, r1.w};
#pragma unroll
                    for (int j = 0; j < 8; j++) {
                        float t = rr[j];
                        if (rscSlot >= 0)
                            t = t * g_aff[rscSlot * 128 + colb + j]
                                  + g_aff[(rscSlot + 1) * 128 + colb + j];
                        v[j] += t;
                    }
                }
                if (doRelu) {
#pragma unroll
                    for (int j = 0; j < 8; j++) v[j] = fmaxf(v[j], 0.f);
                }
                if (C) {
                    *(float4*)(C + (size_t)row * ldc + colb)     = make_float4(v[0], v[1], v[2], v[3]);
                    *(float4*)(C + (size_t)row * ldc + colb + 4) = make_float4(v[4], v[5], v[6], v[7]);
                }
                if (CH) {
                    BF8 h, l;
#pragma unroll
                    for (int j = 0; j < 8; j++) {
                        bf16 hh = __float2bfloat16(v[j]);
                        h.b[j] = hh;
                        l.b[j] = __float2bfloat16(v[j] - __bfloat162float(hh));
                    }
                    *(uint4*)(CH + (size_t)row * ldc + colb) = h.u4;
                    *(uint4*)(CL + (size_t)row * ldc + colb) = l.u4;
                }
            }
            __syncwarp();
        }
}

// ------------------------- batchnorm stats / apply ---------------------------
__global__ void k_stats(int bid, int n, int slot) {
    const float* h = fbptr(bid);
    int c = threadIdx.x;
    float s = 0.f, s2 = 0.f;
    for (int r = blockIdx.x; r < n; r += gridDim.x) {
        float v = h[(size_t)r * 128 + c];
        s += v; s2 += v * v;
    }
    atomicAdd(&g_red[slot * 128 + c], s);
    atomicAdd(&g_red[(slot + 1) * 128 + c], s2);
}

__global__ void k_stats_ext(const float* __restrict__ h, int n, int slot) {
    int c = threadIdx.x;
    float s = 0.f, s2 = 0.f;
    for (int r = blockIdx.x; r < n; r += gridDim.x) {
        float v = h[(size_t)r * 128 + c];
        s += v; s2 += v * v;
    }
    atomicAdd(&g_red[slot * 128 + c], s);
    atomicAdd(&g_red[(slot + 1) * 128 + c], s2);
}

__global__ void k_fin(int slot, const float* __restrict__ gam,
                      const float* __restrict__ bet, int aslot, int n) {
    int c = threadIdx.x;
    float mean = g_red[slot * 128 + c] / (float)n;
    float var  = g_red[(slot + 1) * 128 + c] / (float)n - mean * mean;
    float inv  = rsqrtf(var + 1e-5f);
    float sc   = gam[c] * inv;
    g_aff[aslot * 128 + c]       = sc;
    g_aff[(aslot + 1) * 128 + c] = bet[c] - mean * sc;
}

__global__ void k_apply(float* __restrict__ out, int total) {
    int i = blockIdx.x * blockDim.x + threadIdx.x;
    if (i < total) {
        int c = i & 127;
        out[i] = out[i] * g_aff[256 + c] + g_aff[384 + c];
    }
}

// ------------------------------- launcher ------------------------------------
extern "C" void kernel_launch(void* const* d_in, const int* in_sizes, int n_in,
                              void* d_out, int out_size) {
    const float* x   = (const float*)d_in[0];
    const void*  ei  = d_in[1];
    const float* WQ  = (const float*)d_in[2];
    const float* WK  = (const float*)d_in[3];
    const float* WV  = (const float*)d_in[4];
    const float* WO  = (const float*)d_in[5];
    const float* bO  = (const float*)d_in[6];
    const float* W1  = (const float*)d_in[7];
    const float* b1  = (const float*)d_in[8];
    const float* W2  = (const float*)d_in[9];
    const float* b2  = (const float*)d_in[10];
    const float* g1v = (const float*)d_in[11];
    const float* be1 = (const float*)d_in[12];
    const float* g2v = (const float*)d_in[13];
    const float* be2 = (const float*)d_in[14];

    int n = in_sizes[0] / 128;
    int e = in_sizes[1] / 2;
    float* out = (float*)d_out;

    int nb = (n + 1023) / 1024;

    // prep: dtype detect, x split, weight split, CSR build
    k_detect <<<1, 32>>>(ei, e);
    k_split_x<<<(n * 32 + 255) / 256, 256>>>(x, n * 32);
    k_prepw  <<<256, 256>>>(WQ, WK, WV, WO, W2);
    k_zero   <<<(n + 255) / 256, 256>>>(n);
    k_hist   <<<(e + 255) / 256, 256>>>(ei, e);
    k_scan1  <<<nb, 1024>>>(n);
    k_scan2  <<<1, 32>>>(nb);
    k_scan3  <<<nb, 1024>>>(n, e);
    k_scatter<<<(e + 255) / 256, 256>>>(ei, e);

    dim3 gQKV((n + 127) / 128, 3);
    dim3 g1g((n + 127) / 128, 1);
    dim3 g2g((n + 127) / 128, 2);

    // QKV: x @ [WQ|WK|WV] -> g_qkv fp32 [N,384]
    pgemm<<<gQKV, 256>>>(0, 8, 384, 0, 0, -1, n, 128, 384,
                         0, -1, 0, -1, 0, 0, -1, 0);

    // segment softmax attention -> agg split
    k_attn<<<(n + 7) / 8, 256>>>(n);

    // h1 = agg @ WO + bO + x  -> buf1 fp32 + b1 split
    pgemm<<<g1g, 256>>>(2, 10, 128, 0, 1, 4, n, 128, 128,
                        bO, -1, x, -1, 1, 128, -1, 0);

    // BN1 stats -> sc1/sh1 (g_aff slots 0/1)
    k_stats<<<512, 128>>>(1, n, 0);
    k_fin  <<<1, 128>>>(0, g1v, be1, 0, n);

    // fold BN1 into W1 side
    k_prepw1<<<128, 256>>>(W1);
    k_foldb1<<<1, 256>>>(W1, b1);

    // hidden = relu( h1 @ W1' + b1fold ) -> b2 split
    pgemm<<<g2g, 256>>>(4, 12, 256, 0, -1, 6, n, 128, 256,
                        0, 2, 0, -1, 0, 0, -1, 1);

    // out = hidden @ W2 + b2 + BN1(h1)   (pre-BN2)
    pgemm<<<g1g, 256>>>(6, 14, 128, out, -1, -1, n, 256, 128,
                        b2, -1, 0, 1, 1, 128, 0, 0);

    // BN2 stats -> apply in place
    k_stats_ext<<<512, 128>>>(out, n, 2);
    k_fin      <<<1, 128>>>(2, g2v, be2, 2, n);
    k_apply    <<<(n * 128 + 255) / 256, 256>>>(out, n * 128);
}

// round 8
// speedup vs baseline: 1.6975x; 1.0045x over previous
#include <cuda_runtime.h>
#include <cuda_bf16.h>
#include <mma.h>
using namespace nvcuda;

#define NMAX 50000
#define EMAX 500000
#define NPAD (NMAX + 128)

typedef unsigned long long u64;
typedef __nv_bfloat16 bf16;

// ---------------- device scratch (static allocations, allowed) --------------
__device__ float g_qkv [(size_t)NMAX * 384];    // Q|K|V fp32 (attention input)
__device__ float g_buf1[(size_t)NMAX * 128];    // h1 fp32 (residual for FFN2)
__device__ float g_b1fold[256];                 // b1 + sh1^T W1

__device__ __align__(16) bf16 g_xh  [(size_t)NPAD * 128];
__device__ __align__(16) bf16 g_xl  [(size_t)NPAD * 128];
__device__ __align__(16) bf16 g_aggh[(size_t)NPAD * 128];
__device__ __align__(16) bf16 g_aggl[(size_t)NPAD * 128];
__device__ __align__(16) bf16 g_b1h [(size_t)NPAD * 128];
__device__ __align__(16) bf16 g_b1l [(size_t)NPAD * 128];
__device__ __align__(16) bf16 g_b2h [(size_t)NPAD * 256];
__device__ __align__(16) bf16 g_b2l [(size_t)NPAD * 256];
__device__ __align__(16) bf16 g_wqkvh[128 * 384];
__device__ __align__(16) bf16 g_wqkvl[128 * 384];
__device__ __align__(16) bf16 g_woh [128 * 128];
__device__ __align__(16) bf16 g_wol [128 * 128];
__device__ __align__(16) bf16 g_w1h [128 * 256];
__device__ __align__(16) bf16 g_w1l [128 * 256];
__device__ __align__(16) bf16 g_w2h [256 * 128];
__device__ __align__(16) bf16 g_w2l [256 * 128];

__device__ int   g_cnt   [NMAX];
__device__ int   g_rp    [NMAX + 1];
__device__ int   g_cursor[NMAX];
__device__ int   g_srcs  [EMAX];
__device__ int   g_bsum  [256];
__device__ int   g_is64;
__device__ float g_red[512];
__device__ float g_aff[512];

__device__ __forceinline__ bf16* bfptr(int id) {
    switch (id) {
        case 0:  return g_xh;    case 1:  return g_xl;
        case 2:  return g_aggh;  case 3:  return g_aggl;
        case 4:  return g_b1h;   case 5:  return g_b1l;
        case 6:  return g_b2h;   case 7:  return g_b2l;
        case 8:  return g_wqkvh; case 9:  return g_wqkvl;
        case 10: return g_woh;   case 11: return g_wol;
        case 12: return g_w1h;   case 13: return g_w1l;
        case 14: return g_w2h;   case 15: return g_w2l;
    }
    return 0;
}

__device__ __forceinline__ float* fbptr(int id) {
    switch (id) {
        case 0: return g_qkv;
        case 1: return g_buf1;
        case 2: return g_b1fold;
    }
    return 0;
}

__device__ __forceinline__ int edge_at(const void* ei, size_t idx) {
    if (g_is64) return (int)((const long long*)ei)[idx];
    return ((const int*)ei)[idx];
}

union BF4 { bf16 b[4]; u64 uu; };
union BF8 { bf16 b[8]; uint4 u4; };

__device__ __forceinline__ void cp16(void* smem, const void* gmem) {
    unsigned sa = (unsigned)__cvta_generic_to_shared(smem);
    asm volatile("cp.async.cg.shared.global [%0], [%1], 16;\n" :: "r"(sa), "l"(gmem));
}
#define CP_COMMIT() asm volatile("cp.async.commit_group;\n" ::: "memory")
#define CP_WAIT0()  asm volatile("cp.async.wait_group 0;\n" ::: "memory")

// ---------------------------- small kernels ---------------------------------
__global__ void k_detect(const void* ei, int e) {
    if (threadIdx.x == 0) {
        const long long* p = (const long long*)ei;
        int m = e < 256 ? e : 256;
        int ok = 1;
        for (int i = 0; i < m; i++) {
            long long v = p[i];
            if (v < 0 || v >= NMAX) { ok = 0; break; }
        }
        g_is64 = ok;
    }
}

__global__ void k_split_x(const float* __restrict__ x, int total4) {
    int i = blockIdx.x * blockDim.x + threadIdx.x;
    if (i < total4) {
        float4 v = *(const float4*)(x + i * 4);
        float vv[4] = {v.x, v.y, v.z, v.w};
        BF4 h, l;
#pragma unroll
        for (int j = 0; j < 4; j++) {
            bf16 hh = __float2bfloat16(vv[j]);
            h.b[j] = hh;
            l.b[j] = __float2bfloat16(vv[j] - __bfloat162float(hh));
        }
        *(u64*)(g_xh + i * 4) = h.uu;
        *(u64*)(g_xl + i * 4) = l.uu;
    }
}

__device__ __forceinline__ void splitw(float v, bf16* ph, bf16* pl) {
    bf16 h = __float2bfloat16(v);
    *ph = h;
    *pl = __float2bfloat16(v - __bfloat162float(h));
}

__global__ void k_prepw(const float* __restrict__ WQ, const float* __restrict__ WK,
                        const float* __restrict__ WV, const float* __restrict__ WO,
                        const float* __restrict__ W2) {
    int i = blockIdx.x * 256 + threadIdx.x;
    if (i < 16384) {
        int k = i >> 7, m = i & 127;
        splitw(WQ[i], &g_wqkvh[k * 384 + m],       &g_wqkvl[k * 384 + m]);
        splitw(WK[i], &g_wqkvh[k * 384 + 128 + m], &g_wqkvl[k * 384 + 128 + m]);
        splitw(WV[i], &g_wqkvh[k * 384 + 256 + m], &g_wqkvl[k * 384 + 256 + m]);
    } else if (i < 32768) {
        int j = i - 16384;
        splitw(WO[j], &g_woh[j], &g_wol[j]);
    } else if (i < 65536) {
        int j = i - 32768;
        splitw(W2[j], &g_w2h[j], &g_w2l[j]);
    }
}

// w1' = diag(sc1) @ W1, split. Run AFTER BN1 finalize.
__global__ void k_prepw1(const float* __restrict__ W1) {
    int i = blockIdx.x * 256 + threadIdx.x;
    if (i < 128 * 256) {
        int k = i >> 8;
        splitw(g_aff[k] * W1[i], &g_w1h[i], &g_w1l[i]);
    }
}

// b1fold[c] = b1[c] + sum_k sh1[k] * W1[k][c]
__global__ void k_foldb1(const float* __restrict__ W1, const float* __restrict__ b1) {
    int c = threadIdx.x;    // 256 threads
    float s = b1[c];
    for (int k = 0; k < 128; k++) s += g_aff[128 + k] * W1[k * 256 + c];
    g_b1fold[c] = s;
}

__global__ void k_zero(int n) {
    int i = blockIdx.x * blockDim.x + threadIdx.x;
    if (i < n)   g_cnt[i] = 0;
    if (i < 512) g_red[i] = 0.f;
}

__global__ void k_hist(const void* ei, int e) {
    int i = blockIdx.x * blockDim.x + threadIdx.x;
    if (i < e) atomicAdd(&g_cnt[edge_at(ei, (size_t)e + i)], 1);
}

__global__ void k_scan1(int n) {
    __shared__ int sh[1024];
    int t = threadIdx.x;
    int idx = blockIdx.x * 1024 + t;
    int v = (idx < n) ? g_cnt[idx] : 0;
    sh[t] = v;
    __syncthreads();
    for (int off = 1; off < 1024; off <<= 1) {
        int add = (t >= off) ? sh[t - off] : 0;
        __syncthreads();
        sh[t] += add;
        __syncthreads();
    }
    if (idx < n) g_rp[idx] = sh[t] - v;
    if (t == 1023) g_bsum[blockIdx.x] = sh[1023];
}

__global__ void k_scan2(int nb) {
    if (threadIdx.x == 0) {
        int run = 0;
        for (int i = 0; i < nb; i++) { int c = g_bsum[i]; g_bsum[i] = run; run += c; }
    }
}

__global__ void k_scan3(int n, int e) {
    int idx = blockIdx.x * 1024 + threadIdx.x;
    if (idx < n) {
        int v = g_rp[idx] + g_bsum[blockIdx.x];
        g_rp[idx] = v;
        g_cursor[idx] = v;
    }
    if (idx == 0) g_rp[n] = e;
}

__global__ void k_scatter(const void* ei, int e) {
    int i = blockIdx.x * blockDim.x + threadIdx.x;
    if (i < e) {
        int d = edge_at(ei, (size_t)e + i);
        int s = edge_at(ei, (size_t)i);
        int p = atomicAdd(&g_cursor[d], 1);
        g_srcs[p] = s;
    }
}

// ---------------- attention: one warp per destination node ------------------
// Software pipeline: next pair's indices AND K/V rows prefetched while the
// current pair computes (doubles loads in flight on the L2 gather path).
__global__ void k_attn(int n) {
    int warp = (blockIdx.x * blockDim.x + threadIdx.x) >> 5;
    int lane = threadIdx.x & 31;
    if (warp >= n) return;

    float4 q = *(const float4*)(g_qkv + (size_t)warp * 384 + lane * 4);

    float ax = 0.f, ay = 0.f, az = 0.f, aw = 0.f, se = 0.f;
    int beg = g_rp[warp], end = g_rp[warp + 1];

    int p = beg;
    int ja = (p     < end) ? g_srcs[p]     : -1;
    int jb = (p + 1 < end) ? g_srcs[p + 1] : -1;
    float4 ka = make_float4(0.f, 0.f, 0.f, 0.f), va = ka, kb = ka, vb = ka;
    if (ja >= 0) {
        const float* b = g_qkv + (size_t)ja * 384;
        ka = *(const float4*)(b + 128 + lane * 4);
        va = *(const float4*)(b + 256 + lane * 4);
    }
    if (jb >= 0) {
        const float* b = g_qkv + (size_t)jb * 384;
        kb = *(const float4*)(b + 128 + lane * 4);
        vb = *(const float4*)(b + 256 + lane * 4);
    }

    while (ja >= 0) {
        // prefetch pair (p+2, p+3)
        int jc = (p + 2 < end) ? g_srcs[p + 2] : -1;
        int jd = (p + 3 < end) ? g_srcs[p + 3] : -1;
        float4 kc = make_float4(0.f, 0.f, 0.f, 0.f), vc = kc, kd = kc, vd = kc;
        if (jc >= 0) {
            const float* b = g_qkv + (size_t)jc * 384;
            kc = *(const float4*)(b + 128 + lane * 4);
            vc = *(const float4*)(b + 256 + lane * 4);
        }
        if (jd >= 0) {
            const float* b = g_qkv + (size_t)jd * 384;
            kd = *(const float4*)(b + 128 + lane * 4);
            vd = *(const float4*)(b + 256 + lane * 4);
        }

        // compute current pair (kb/vb are zeros when jb < 0 -> e1 masked to 0)
        float m1 = (jb >= 0) ? 1.f : 0.f;
        float s0 = q.x * ka.x + q.y * ka.y + q.z * ka.z + q.w * ka.w;
        float s1 = q.x * kb.x + q.y * kb.y + q.z * kb.z + q.w * kb.w;
        s0 += __shfl_xor_sync(0xffffffffu, s0, 1);
        s1 += __shfl_xor_sync(0xffffffffu, s1, 1);
        s0 += __shfl_xor_sync(0xffffffffu, s0, 2);
        s1 += __shfl_xor_sync(0xffffffffu, s1, 2);
        s0 = fminf(fmaxf(s0 * 0.25f, -5.f), 5.f);
        s1 = fminf(fmaxf(s1 * 0.25f, -5.f), 5.f);
        float e0 = __expf(s0);
        float e1 = __expf(s1) * m1;
        ax += e0 * va.x + e1 * vb.x;
        ay += e0 * va.y + e1 * vb.y;
        az += e0 * va.z + e1 * vb.z;
        aw += e0 * va.w + e1 * vb.w;
        se += e0 + e1;

        ja = jc; ka = kc; va = vc;
        jb = jd; kb = kd; vb = vd;
        p += 2;
    }

    float inv = 1.0f / (se + 1e-16f);
    float o[4] = {ax * inv, ay * inv, az * inv, aw * inv};
    BF4 oh, ol;
#pragma unroll
    for (int j = 0; j < 4; j++) {
        bf16 h = __float2bfloat16(o[j]);
        oh.b[j] = h;
        ol.b[j] = __float2bfloat16(o[j] - __bfloat162float(h));
    }
    *(u64*)(g_aggh + (size_t)warp * 128 + lane * 4) = oh.uu;
    *(u64*)(g_aggl + (size_t)warp * 128 + lane * 4) = ol.uu;
}

// ------ tensor-core GEMM: bf16 3-term split, cp.async double-buffered -------
// Optional fused per-column stats (sum, sumsq) for BatchNorm via statsSlot.
struct PipeBufs {
    unsigned short AsH[2][128][24];
    unsigned short AsL[2][128][24];
    unsigned short WsH[2][16][136];
    unsigned short WsL[2][16][136];
};
union SmemU {
    PipeBufs p;
    float Cs[8][16][16];
};

__global__ __launch_bounds__(256) void pgemm(
    int AHid, int WHid, int Wld,
    float* Cext, int Cid, int CHid,
    int nrows, int K, int ldc,
    const float* biasExt, int biasId,
    const float* Rext, int rid, int hasResid, int ldres, int rscSlot,
    int doRelu, int statsSlot)
{
    __shared__ __align__(16) SmemU sm;
    __shared__ float sSum[128], sSq[128];

    const bf16* AH = bfptr(AHid);
    const bf16* AL = bfptr(AHid + 1);
    const bf16* WH = bfptr(WHid);
    const bf16* WL = bfptr(WHid + 1);
    float* C = (Cid >= 0) ? fbptr(Cid) : Cext;
    bf16* CH = (CHid >= 0) ? bfptr(CHid) : 0;
    bf16* CL = (CHid >= 0) ? bfptr(CHid + 1) : 0;
    const float* bias = (biasId >= 0) ? fbptr(biasId) : biasExt;
    const float* resid = hasResid ? ((rid >= 0) ? fbptr(rid) : Rext) : 0;

    int tid  = threadIdx.x;
    int warp = tid >> 5;
    int lane = tid & 31;
    int rowBase = blockIdx.x * 128;
    int colBase = blockIdx.y * 128;

    int wRow = (warp >> 2) * 64;
    int wCol = (warp & 3) * 32;

    if (statsSlot >= 0 && tid < 128) { sSum[tid] = 0.f; sSq[tid] = 0.f; }

    int ar = tid >> 1;
    int ak = (tid & 1) * 8;
    int wr = tid >> 4;
    int wc = (tid & 15) * 8;

    wmma::fragment<wmma::accumulator, 16, 16, 16, float> acc[4][2];
#pragma unroll
    for (int i = 0; i < 4; i++)
#pragma unroll
        for (int j = 0; j < 2; j++) wmma::fill_fragment(acc[i][j], 0.f);

    const size_t aOff = (size_t)(rowBase + ar) * K + ak;

    cp16(&sm.p.AsH[0][ar][ak], AH + aOff);
    cp16(&sm.p.AsL[0][ar][ak], AL + aOff);
    cp16(&sm.p.WsH[0][wr][wc], WH + (size_t)wr * Wld + colBase + wc);
    cp16(&sm.p.WsL[0][wr][wc], WL + (size_t)wr * Wld + colBase + wc);
    CP_COMMIT();

    int nIter = K >> 4;
    for (int it = 0; it < nIter; it++) {
        int st = it & 1;
        CP_WAIT0();
        __syncthreads();

        int kn = (it + 1) << 4;
        if (kn < K) {
            int sn = st ^ 1;
            cp16(&sm.p.AsH[sn][ar][ak], AH + aOff + kn);
            cp16(&sm.p.AsL[sn][ar][ak], AL + aOff + kn);
            cp16(&sm.p.WsH[sn][wr][wc], WH + (size_t)(kn + wr) * Wld + colBase + wc);
            cp16(&sm.p.WsL[sn][wr][wc], WL + (size_t)(kn + wr) * Wld + colBase + wc);
            CP_COMMIT();
        }

        wmma::fragment<wmma::matrix_a, 16, 16, 16, bf16, wmma::row_major> aH[4], aL[4];
        wmma::fragment<wmma::matrix_b, 16, 16, 16, bf16, wmma::row_major> bH[2], bL[2];
#pragma unroll
        for (int mi = 0; mi < 4; mi++) {
            wmma::load_matrix_sync(aH[mi], (const bf16*)&sm.p.AsH[st][wRow + mi * 16][0], 24);
            wmma::load_matrix_sync(aL[mi], (const bf16*)&sm.p.AsL[st][wRow + mi * 16][0], 24);
        }
#pragma unroll
        for (int ni = 0; ni < 2; ni++) {
            wmma::load_matrix_sync(bH[ni], (const bf16*)&sm.p.WsH[st][0][wCol + ni * 16], 136);
            wmma::load_matrix_sync(bL[ni], (const bf16*)&sm.p.WsL[st][0][wCol + ni * 16], 136);
        }
#pragma unroll
        for (int mi = 0; mi < 4; mi++)
#pragma unroll
            for (int ni = 0; ni < 2; ni++) {
                wmma::mma_sync(acc[mi][ni], aH[mi], bL[ni], acc[mi][ni]);
                wmma::mma_sync(acc[mi][ni], aL[mi], bH[ni], acc[mi][ni]);
                wmma::mma_sync(acc[mi][ni], aH[mi], bH[ni], acc[mi][ni]);
            }
    }

    __syncthreads();   // before Cs aliases pipeline buffers

    // fused epilogue via per-warp smem scratch (+ optional column stats)
#pragma unroll
    for (int mi = 0; mi < 4; mi++)
#pragma unroll
        for (int ni = 0; ni < 2; ni++) {
            wmma::store_matrix_sync(&sm.Cs[warp][0][0], acc[mi][ni], 16, wmma::mem_row_major);
            __syncwarp();
            int r16 = lane >> 1;
            int c0  = (lane & 1) * 8;
            int row = rowBase + wRow + mi * 16 + r16;
            float v[8];
#pragma unroll
            for (int j = 0; j < 8; j++) v[j] = 0.f;
            int colb = colBase + wCol + ni * 16 + c0;
            if (row < nrows) {
#pragma unroll
                for (int j = 0; j < 8; j++) {
                    v[j] = sm.Cs[warp][r16][c0 + j];
                    if (bias) v[j] += bias[colb + j];
                }
                if (resid) {
                    float4 r0 = *(const float4*)(resid + (size_t)row * ldres + colb);
                    float4 r1 = *(const float4*)(resid + (size_t)row * ldres + colb + 4);
                    float rr[8] = {r0.x, r0.y, r0.z, r0.w, r1.x, r1.y, r1.z, r1.w};
#pragma unroll
                    for (int j = 0; j < 8; j++) {
                        float t = rr[j];
                        if (rscSlot >= 0)
                            t = t * g_aff[rscSlot * 128 + colb + j]
                                  + g_aff[(rscSlot + 1) * 128 + colb + j];
                        v[j] += t;
                    }
                }
                if (doRelu) {
#pragma unroll
                    for (int j = 0; j < 8; j++) v[j] = fmaxf(v[j], 0.f);
                }
                if (C) {
                    *(float4*)(C + (size_t)row * ldc + colb)     = make_float4(v[0], v[1], v[2], v[3]);
                    *(float4*)(C + (size_t)row * ldc + colb + 4) = make_float4(v[4], v[5], v[6], v[7]);
                }
                if (CH) {
                    BF8 h, l;
#pragma unroll
                    for (int j = 0; j < 8; j++) {
                        bf16 hh = __float2bfloat16(v[j]);
                        h.b[j] = hh;
                        l.b[j] = __float2bfloat16(v[j] - __bfloat162float(hh));
                    }
                    *(uint4*)(CH + (size_t)row * ldc + colb) = h.u4;
                    *(uint4*)(CL + (size_t)row * ldc + colb) = l.u4;
                }
            }
            if (statsSlot >= 0) {
                // reduce v and v^2 down the 16 rows (lanes with same parity)
#pragma unroll
                for (int j = 0; j < 8; j++) {
                    float sv = v[j];
                    float qv = v[j] * v[j];
#pragma unroll
                    for (int m = 2; m <= 16; m <<= 1) {
                        sv += __shfl_xor_sync(0xffffffffu, sv, m);
                        qv += __shfl_xor_sync(0xffffffffu, qv, m);
                    }
                    if (lane < 2) {
                        int cc = wCol + ni * 16 + (lane ? 8 : 0) + j;
                        atomicAdd(&sSum[cc], sv);
                        atomicAdd(&sSq[cc], qv);
                    }
                }
            }
            __syncwarp();
        }

    if (statsSlot >= 0) {
        __syncthreads();
        if (tid < 128)       atomicAdd(&g_red[statsSlot * 128 + tid], sSum[tid]);
        else if (tid < 256)  atomicAdd(&g_red[(statsSlot + 1) * 128 + tid - 128], sSq[tid - 128]);
    }
}

// ------------------------- batchnorm finalize / apply ------------------------
__global__ void k_fin(int slot, const float* __restrict__ gam,
                      const float* __restrict__ bet, int aslot, int n) {
    int c = threadIdx.x;
    float mean = g_red[slot * 128 + c] / (float)n;
    float var  = g_red[(slot + 1) * 128 + c] / (float)n - mean * mean;
    float inv  = rsqrtf(var + 1e-5f);
    float sc   = gam[c] * inv;
    g_aff[aslot * 128 + c]       = sc;
    g_aff[(aslot + 1) * 128 + c] = bet[c] - mean * sc;
}

__global__ void k_apply(float* __restrict__ out, int total) {
    int i = blockIdx.x * blockDim.x + threadIdx.x;
    if (i < total) {
        int c = i & 127;
        out[i] = out[i] * g_aff[256 + c] + g_aff[384 + c];
    }
}

// ------------------------------- launcher ------------------------------------
extern "C" void kernel_launch(void* const* d_in, const int* in_sizes, int n_in,
                              void* d_out, int out_size) {
    const float* x   = (const float*)d_in[0];
    const void*  ei  = d_in[1];
    const float* WQ  = (const float*)d_in[2];
    const float* WK  = (const float*)d_in[3];
    const float* WV  = (const float*)d_in[4];
    const float* WO  = (const float*)d_in[5];
    const float* bO  = (const float*)d_in[6];
    const float* W1  = (const float*)d_in[7];
    const float* b1  = (const float*)d_in[8];
    const float* W2  = (const float*)d_in[9];
    const float* b2  = (const float*)d_in[10];
    const float* g1v = (const float*)d_in[11];
    const float* be1 = (const float*)d_in[12];
    const float* g2v = (const float*)d_in[13];
    const float* be2 = (const float*)d_in[14];

    int n = in_sizes[0] / 128;
    int e = in_sizes[1] / 2;
    float* out = (float*)d_out;

    int nb = (n + 1023) / 1024;

    // prep: dtype detect, x split, weight split, CSR build
    k_detect <<<1, 32>>>(ei, e);
    k_split_x<<<(n * 32 + 255) / 256, 256>>>(x, n * 32);
    k_prepw  <<<256, 256>>>(WQ, WK, WV, WO, W2);
    k_zero   <<<(n + 255) / 256, 256>>>(n);
    k_hist   <<<(e + 255) / 256, 256>>>(ei, e);
    k_scan1  <<<nb, 1024>>>(n);
    k_scan2  <<<1, 32>>>(nb);
    k_scan3  <<<nb, 1024>>>(n, e);
    k_scatter<<<(e + 255) / 256, 256>>>(ei, e);

    dim3 gQKV((n + 127) / 128, 3);
    dim3 g1g((n + 127) / 128, 1);
    dim3 g2g((n + 127) / 128, 2);

    // QKV: x @ [WQ|WK|WV] -> g_qkv fp32 [N,384]
    pgemm<<<gQKV, 256>>>(0, 8, 384, 0, 0, -1, n, 128, 384,
                         0, -1, 0, -1, 0, 0, -1, 0, -1);

    // segment softmax attention -> agg split
    k_attn<<<(n + 7) / 8, 256>>>(n);

    // h1 = agg @ WO + bO + x  -> buf1 fp32 + b1 split, BN1 stats fused
    pgemm<<<g1g, 256>>>(2, 10, 128, 0, 1, 4, n, 128, 128,
                        bO, -1, x, -1, 1, 128, -1, 0, 0);

    // BN1 finalize -> sc1/sh1 (g_aff slots 0/1)
    k_fin<<<1, 128>>>(0, g1v, be1, 0, n);

    // fold BN1 into W1 side
    k_prepw1<<<128, 256>>>(W1);
    k_foldb1<<<1, 256>>>(W1, b1);

    // hidden = relu( h1 @ W1' + b1fold ) -> b2 split
    pgemm<<<g2g, 256>>>(4, 12, 256, 0, -1, 6, n, 128, 256,
                        0, 2, 0, -1, 0, 0, -1, 1, -1);

    // out = hidden @ W2 + b2 + BN1(h1)  (pre-BN2), BN2 stats fused
    pgemm<<<g1g, 256>>>(6, 14, 128, out, -1, -1, n, 256, 128,
                        b2, -1, 0, 1, 1, 128, 0, 0, 2);

    // BN2 finalize -> apply in place
    k_fin  <<<1, 128>>>(2, g2v, be2, 2, n);
    k_apply<<<(n * 128 + 255) / 256, 256>>>(out, n * 128);
}

// round 9
// speedup vs baseline: 1.8478x; 1.0885x over previous
#include <cuda_runtime.h>
#include <cuda_bf16.h>
#include <mma.h>
using namespace nvcuda;

#define NMAX 50000
#define EMAX 500000
#define NPAD (NMAX + 128)

typedef unsigned long long u64;
typedef __nv_bfloat16 bf16;

// ---------------- device scratch (static allocations, allowed) --------------
__device__ float g_qkv [(size_t)NMAX * 384];    // Q|K|V fp32 (attention input)
__device__ float g_buf1[(size_t)NMAX * 128];    // h1 fp32 (residual for FFN2)
__device__ float g_b1fold[256];                 // b1 + sh1^T W1

__device__ __align__(16) bf16 g_xh  [(size_t)NPAD * 128];
__device__ __align__(16) bf16 g_xl  [(size_t)NPAD * 128];
__device__ __align__(16) bf16 g_aggh[(size_t)NPAD * 128];
__device__ __align__(16) bf16 g_aggl[(size_t)NPAD * 128];
__device__ __align__(16) bf16 g_b1h [(size_t)NPAD * 128];
__device__ __align__(16) bf16 g_b1l [(size_t)NPAD * 128];
__device__ __align__(16) bf16 g_b2h [(size_t)NPAD * 256];
__device__ __align__(16) bf16 g_b2l [(size_t)NPAD * 256];
__device__ __align__(16) bf16 g_wqkvh[128 * 384];
__device__ __align__(16) bf16 g_wqkvl[128 * 384];
__device__ __align__(16) bf16 g_woh [128 * 128];
__device__ __align__(16) bf16 g_wol [128 * 128];
__device__ __align__(16) bf16 g_w1h [128 * 256];
__device__ __align__(16) bf16 g_w1l [128 * 256];
__device__ __align__(16) bf16 g_w2h [256 * 128];
__device__ __align__(16) bf16 g_w2l [256 * 128];

__device__ int   g_cnt   [NMAX];
__device__ int   g_rp    [NMAX + 1];
__device__ int   g_cursor[NMAX];
__device__ int   g_srcs  [EMAX];
__device__ int   g_bsum  [256];
__device__ int   g_is64;
__device__ float g_red[512];
__device__ float g_aff[512];

__device__ __forceinline__ bf16* bfptr(int id) {
    switch (id) {
        case 0:  return g_xh;    case 1:  return g_xl;
        case 2:  return g_aggh;  case 3:  return g_aggl;
        case 4:  return g_b1h;   case 5:  return g_b1l;
        case 6:  return g_b2h;   case 7:  return g_b2l;
        case 8:  return g_wqkvh; case 9:  return g_wqkvl;
        case 10: return g_woh;   case 11: return g_wol;
        case 12: return g_w1h;   case 13: return g_w1l;
        case 14: return g_w2h;   case 15: return g_w2l;
    }
    return 0;
}

__device__ __forceinline__ float* fbptr(int id) {
    switch (id) {
        case 0: return g_qkv;
        case 1: return g_buf1;
        case 2: return g_b1fold;
    }
    return 0;
}

__device__ __forceinline__ int edge_at(const void* ei, size_t idx) {
    if (g_is64) return (int)((const long long*)ei)[idx];
    return ((const int*)ei)[idx];
}

union BF4 { bf16 b[4]; u64 uu; };
union BF8 { bf16 b[8]; uint4 u4; };

__device__ __forceinline__ void cp16(void* smem, const void* gmem) {
    unsigned sa = (unsigned)__cvta_generic_to_shared(smem);
    asm volatile("cp.async.cg.shared.global [%0], [%1], 16;\n" :: "r"(sa), "l"(gmem));
}
#define CP_COMMIT() asm volatile("cp.async.commit_group;\n" ::: "memory")
#define CP_WAIT0()  asm volatile("cp.async.wait_group 0;\n" ::: "memory")

// --------------------- streams/events for fork-join capture ------------------
static cudaStream_t g_s2;
static cudaEvent_t  g_e1, g_e2;
static struct StreamInit {
    StreamInit() {
        cudaStreamCreateWithFlags(&g_s2, cudaStreamNonBlocking);
        cudaEventCreateWithFlags(&g_e1, cudaEventDisableTiming);
        cudaEventCreateWithFlags(&g_e2, cudaEventDisableTiming);
    }
} g_streamInit;

// ---------------------------- small kernels ---------------------------------
// detect edge dtype (block 0) + zero g_cnt/g_red
__global__ void k_init(const void* ei, int e, int n) {
    int i = blockIdx.x * blockDim.x + threadIdx.x;
    if (blockIdx.x == 0) {
        const long long* p = (const long long*)ei;
        int m = e < 256 ? e : 256;
        int bad = 0;
        if (threadIdx.x < m) {
            long long v = p[threadIdx.x];
            bad = (v < 0 || v >= NMAX);
        }
        int any = __syncthreads_or(bad);
        if (threadIdx.x == 0) g_is64 = !any;
    }
    if (i < n)   g_cnt[i] = 0;
    if (i < 512) g_red[i] = 0.f;
}

__global__ void k_split_x(const float* __restrict__ x, int total4) {
    int i = blockIdx.x * blockDim.x + threadIdx.x;
    if (i < total4) {
        float4 v = *(const float4*)(x + i * 4);
        float vv[4] = {v.x, v.y, v.z, v.w};
        BF4 h, l;
#pragma unroll
        for (int j = 0; j < 4; j++) {
            bf16 hh = __float2bfloat16(vv[j]);
            h.b[j] = hh;
            l.b[j] = __float2bfloat16(vv[j] - __bfloat162float(hh));
        }
        *(u64*)(g_xh + i * 4) = h.uu;
        *(u64*)(g_xl + i * 4) = l.uu;
    }
}

__device__ __forceinline__ void splitw(float v, bf16* ph, bf16* pl) {
    bf16 h = __float2bfloat16(v);
    *ph = h;
    *pl = __float2bfloat16(v - __bfloat162float(h));
}

__global__ void k_prepw(const float* __restrict__ WQ, const float* __restrict__ WK,
                        const float* __restrict__ WV, const float* __restrict__ WO,
                        const float* __restrict__ W2) {
    int i = blockIdx.x * 256 + threadIdx.x;
    if (i < 16384) {
        int k = i >> 7, m = i & 127;
        splitw(WQ[i], &g_wqkvh[k * 384 + m],       &g_wqkvl[k * 384 + m]);
        splitw(WK[i], &g_wqkvh[k * 384 + 128 + m], &g_wqkvl[k * 384 + 128 + m]);
        splitw(WV[i], &g_wqkvh[k * 384 + 256 + m], &g_wqkvl[k * 384 + 256 + m]);
    } else if (i < 32768) {
        int j = i - 16384;
        splitw(WO[j], &g_woh[j], &g_wol[j]);
    } else if (i < 65536) {
        int j = i - 32768;
        splitw(W2[j], &g_w2h[j], &g_w2l[j]);
    }
}

__global__ void k_hist(const void* ei, int e) {
    int i = blockIdx.x * blockDim.x + threadIdx.x;
    if (i < e) atomicAdd(&g_cnt[edge_at(ei, (size_t)e + i)], 1);
}

__global__ void k_scan1(int n) {
    __shared__ int sh[1024];
    int t = threadIdx.x;
    int idx = blockIdx.x * 1024 + t;
    int v = (idx < n) ? g_cnt[idx] : 0;
    sh[t] = v;
    __syncthreads();
    for (int off = 1; off < 1024; off <<= 1) {
        int add = (t >= off) ? sh[t - off] : 0;
        __syncthreads();
        sh[t] += add;
        __syncthreads();
    }
    if (idx < n) g_rp[idx] = sh[t] - v;
    if (t == 1023) g_bsum[blockIdx.x] = sh[1023];
}

__global__ void k_scan2(int nb) {
    if (threadIdx.x == 0) {
        int run = 0;
        for (int i = 0; i < nb; i++) { int c = g_bsum[i]; g_bsum[i] = run; run += c; }
    }
}

__global__ void k_scan3(int n, int e) {
    int idx = blockIdx.x * 1024 + threadIdx.x;
    if (idx < n) {
        int v = g_rp[idx] + g_bsum[blockIdx.x];
        g_rp[idx] = v;
        g_cursor[idx] = v;
    }
    if (idx == 0) g_rp[n] = e;
}

__global__ void k_scatter(const void* ei, int e) {
    int i = blockIdx.x * blockDim.x + threadIdx.x;
    if (i < e) {
        int d = edge_at(ei, (size_t)e + i);
        int s = edge_at(ei, (size_t)i);
        int p = atomicAdd(&g_cursor[d], 1);
        g_srcs[p] = s;
    }
}

// ---------------- attention: one warp per destination node ------------------
__global__ void k_attn(int n) {
    int warp = (blockIdx.x * blockDim.x + threadIdx.x) >> 5;
    int lane = threadIdx.x & 31;
    if (warp >= n) return;

    float4 q = *(const float4*)(g_qkv + (size_t)warp * 384 + lane * 4);

    float ax = 0.f, ay = 0.f, az = 0.f, aw = 0.f, se = 0.f;
    int beg = g_rp[warp], end = g_rp[warp + 1];

    int p = beg;
    int ja = (p     < end) ? g_srcs[p]     : -1;
    int jb = (p + 1 < end) ? g_srcs[p + 1] : -1;
    float4 ka = make_float4(0.f, 0.f, 0.f, 0.f), va = ka, kb = ka, vb = ka;
    if (ja >= 0) {
        const float* b = g_qkv + (size_t)ja * 384;
        ka = *(const float4*)(b + 128 + lane * 4);
        va = *(const float4*)(b + 256 + lane * 4);
    }
    if (jb >= 0) {
        const float* b = g_qkv + (size_t)jb * 384;
        kb = *(const float4*)(b + 128 + lane * 4);
        vb = *(const float4*)(b + 256 + lane * 4);
    }

    while (ja >= 0) {
        int jc = (p + 2 < end) ? g_srcs[p + 2] : -1;
        int jd = (p + 3 < end) ? g_srcs[p + 3] : -1;
        float4 kc = make_float4(0.f, 0.f, 0.f, 0.f), vc = kc, kd = kc, vd = kc;
        if (jc >= 0) {
            const float* b = g_qkv + (size_t)jc * 384;
            kc = *(const float4*)(b + 128 + lane * 4);
            vc = *(const float4*)(b + 256 + lane * 4);
        }
        if (jd >= 0) {
            const float* b = g_qkv + (size_t)jd * 384;
            kd = *(const float4*)(b + 128 + lane * 4);
            vd = *(const float4*)(b + 256 + lane * 4);
        }

        float m1 = (jb >= 0) ? 1.f : 0.f;
        float s0 = q.x * ka.x + q.y * ka.y + q.z * ka.z + q.w * ka.w;
        float s1 = q.x * kb.x + q.y * kb.y + q.z * kb.z + q.w * kb.w;
        s0 += __shfl_xor_sync(0xffffffffu, s0, 1);
        s1 += __shfl_xor_sync(0xffffffffu, s1, 1);
        s0 += __shfl_xor_sync(0xffffffffu, s0, 2);
        s1 += __shfl_xor_sync(0xffffffffu, s1, 2);
        s0 = fminf(fmaxf(s0 * 0.25f, -5.f), 5.f);
        s1 = fminf(fmaxf(s1 * 0.25f, -5.f), 5.f);
        float e0 = __expf(s0);
        float e1 = __expf(s1) * m1;
        ax += e0 * va.x + e1 * vb.x;
        ay += e0 * va.y + e1 * vb.y;
        az += e0 * va.z + e1 * vb.z;
        aw += e0 * va.w + e1 * vb.w;
        se += e0 + e1;

        ja = jc; ka = kc; va = vc;
        jb = jd; kb = kd; vb = vd;
        p += 2;
    }

    float inv = 1.0f / (se + 1e-16f);
    float o[4] = {ax * inv, ay * inv, az * inv, aw * inv};
    BF4 oh, ol;
#pragma unroll
    for (int j = 0; j < 4; j++) {
        bf16 h = __float2bfloat16(o[j]);
        oh.b[j] = h;
        ol.b[j] = __float2bfloat16(o[j] - __bfloat162float(h));
    }
    *(u64*)(g_aggh + (size_t)warp * 128 + lane * 4) = oh.uu;
    *(u64*)(g_aggl + (size_t)warp * 128 + lane * 4) = ol.uu;
}

// ------ tensor-core GEMM: bf16 3-term split, cp.async double-buffered -------
struct PipeBufs {
    unsigned short AsH[2][128][24];
    unsigned short AsL[2][128][24];
    unsigned short WsH[2][16][136];
    unsigned short WsL[2][16][136];
};
union SmemU {
    PipeBufs p;
    float Cs[8][16][16];
};

__global__ __launch_bounds__(256) void pgemm(
    int AHid, int WHid, int Wld,
    float* Cext, int Cid, int CHid,
    int nrows, int K, int ldc,
    const float* biasExt, int biasId,
    const float* Rext, int rid, int hasResid, int ldres, int rscSlot,
    int doRelu, int statsSlot)
{
    __shared__ __align__(16) SmemU sm;
    __shared__ float sSum[128], sSq[128];

    const bf16* AH = bfptr(AHid);
    const bf16* AL = bfptr(AHid + 1);
    const bf16* WH = bfptr(WHid);
    const bf16* WL = bfptr(WHid + 1);
    float* C = (Cid >= 0) ? fbptr(Cid) : Cext;
    bf16* CH = (CHid >= 0) ? bfptr(CHid) : 0;
    bf16* CL = (CHid >= 0) ? bfptr(CHid + 1) : 0;
    const float* bias = (biasId >= 0) ? fbptr(biasId) : biasExt;
    const float* resid = hasResid ? ((rid >= 0) ? fbptr(rid) : Rext) : 0;

    int tid  = threadIdx.x;
    int warp = tid >> 5;
    int lane = tid & 31;
    int rowBase = blockIdx.x * 128;
    int colBase = blockIdx.y * 128;

    int wRow = (warp >> 2) * 64;
    int wCol = (warp & 3) * 32;

    if (statsSlot >= 0 && tid < 128) { sSum[tid] = 0.f; sSq[tid] = 0.f; }

    int ar = tid >> 1;
    int ak = (tid & 1) * 8;
    int wr = tid >> 4;
    int wc = (tid & 15) * 8;

    wmma::fragment<wmma::accumulator, 16, 16, 16, float> acc[4][2];
#pragma unroll
    for (int i = 0; i < 4; i++)
#pragma unroll
        for (int j = 0; j < 2; j++) wmma::fill_fragment(acc[i][j], 0.f);

    const size_t aOff = (size_t)(rowBase + ar) * K + ak;

    cp16(&sm.p.AsH[0][ar][ak], AH + aOff);
    cp16(&sm.p.AsL[0][ar][ak], AL + aOff);
    cp16(&sm.p.WsH[0][wr][wc], WH + (size_t)wr * Wld + colBase + wc);
    cp16(&sm.p.WsL[0][wr][wc], WL + (size_t)wr * Wld + colBase + wc);
    CP_COMMIT();

    int nIter = K >> 4;
    for (int it = 0; it < nIter; it++) {
        int st = it & 1;
        CP_WAIT0();
        __syncthreads();

        int kn = (it + 1) << 4;
        if (kn < K) {
            int sn = st ^ 1;
            cp16(&sm.p.AsH[sn][ar][ak], AH + aOff + kn);
            cp16(&sm.p.AsL[sn][ar][ak], AL + aOff + kn);
            cp16(&sm.p.WsH[sn][wr][wc], WH + (size_t)(kn + wr) * Wld + colBase + wc);
            cp16(&sm.p.WsL[sn][wr][wc], WL + (size_t)(kn + wr) * Wld + colBase + wc);
            CP_COMMIT();
        }

        wmma::fragment<wmma::matrix_a, 16, 16, 16, bf16, wmma::row_major> aH[4], aL[4];
        wmma::fragment<wmma::matrix_b, 16, 16, 16, bf16, wmma::row_major> bH[2], bL[2];
#pragma unroll
        for (int mi = 0; mi < 4; mi++) {
            wmma::load_matrix_sync(aH[mi], (const bf16*)&sm.p.AsH[st][wRow + mi * 16][0], 24);
            wmma::load_matrix_sync(aL[mi], (const bf16*)&sm.p.AsL[st][wRow + mi * 16][0], 24);
        }
#pragma unroll
        for (int ni = 0; ni < 2; ni++) {
            wmma::load_matrix_sync(bH[ni], (const bf16*)&sm.p.WsH[st][0][wCol + ni * 16], 136);
            wmma::load_matrix_sync(bL[ni], (const bf16*)&sm.p.WsL[st][0][wCol + ni * 16], 136);
        }
#pragma unroll
        for (int mi = 0; mi < 4; mi++)
#pragma unroll
            for (int ni = 0; ni < 2; ni++) {
                wmma::mma_sync(acc[mi][ni], aH[mi], bL[ni], acc[mi][ni]);
                wmma::mma_sync(acc[mi][ni], aL[mi], bH[ni], acc[mi][ni]);
                wmma::mma_sync(acc[mi][ni], aH[mi], bH[ni], acc[mi][ni]);
            }
    }

    __syncthreads();

#pragma unroll
    for (int mi = 0; mi < 4; mi++)
#pragma unroll
        for (int ni = 0; ni < 2; ni++) {
            wmma::store_matrix_sync(&sm.Cs[warp][0][0], acc[mi][ni], 16, wmma::mem_row_major);
            __syncwarp();
            int r16 = lane >> 1;
            int c0  = (lane & 1) * 8;
            int row = rowBase + wRow + mi * 16 + r16;
            float v[8];
#pragma unroll
            for (int j = 0; j < 8; j++) v[j] = 0.f;
            int colb = colBase + wCol + ni * 16 + c0;
            if (row < nrows) {
#pragma unroll
                for (int j = 0; j < 8; j++) {
                    v[j] = sm.Cs[warp][r16][c0 + j];
                    if (bias) v[j] += bias[colb + j];
                }
                if (resid) {
                    float4 r0 = *(const float4*)(resid + (size_t)row * ldres + colb);
                    float4 r1 = *(const float4*)(resid + (size_t)row * ldres + colb + 4);
                    float rr[8] = {r0.x, r0.y, r0.z, r0.w, r1.x, r1.y, r1.z, r1.w};
#pragma unroll
                    for (int j = 0; j < 8; j++) {
                        float t = rr[j];
                        if (rscSlot >= 0)
                            t = t * g_aff[rscSlot * 128 + colb + j]
                                  + g_aff[(rscSlot + 1) * 128 + colb + j];
                        v[j] += t;
                    }
                }
                if (doRelu) {
#pragma unroll
                    for (int j = 0; j < 8; j++) v[j] = fmaxf(v[j], 0.f);
                }
                if (C) {
                    *(float4*)(C + (size_t)row * ldc + colb)     = make_float4(v[0], v[1], v[2], v[3]);
                    *(float4*)(C + (size_t)row * ldc + colb + 4) = make_float4(v[4], v[5], v[6], v[7]);
                }
                if (CH) {
                    BF8 h, l;
#pragma unroll
                    for (int j = 0; j < 8; j++) {
                        bf16 hh = __float2bfloat16(v[j]);
                        h.b[j] = hh;
                        l.b[j] = __float2bfloat16(v[j] - __bfloat162float(hh));
                    }
                    *(uint4*)(CH + (size_t)row * ldc + colb) = h.u4;
                    *(uint4*)(CL + (size_t)row * ldc + colb) = l.u4;
                }
            }
            if (statsSlot >= 0) {
#pragma unroll
                for (int j = 0; j < 8; j++) {
                    float sv = v[j];
                    float qv = v[j] * v[j];
#pragma unroll
                    for (int m = 2; m <= 16; m <<= 1) {
                        sv += __shfl_xor_sync(0xffffffffu, sv, m);
                        qv += __shfl_xor_sync(0xffffffffu, qv, m);
                    }
                    if (lane < 2) {
                        int cc = wCol + ni * 16 + (lane ? 8 : 0) + j;
                        atomicAdd(&sSum[cc], sv);
                        atomicAdd(&sSq[cc], qv);
                    }
                }
            }
            __syncwarp();
        }

    if (statsSlot >= 0) {
        __syncthreads();
        if (tid < 128)       atomicAdd(&g_red[statsSlot * 128 + tid], sSum[tid]);
        else if (tid < 256)  atomicAdd(&g_red[(statsSlot + 1) * 128 + tid - 128], sSq[tid - 128]);
    }
}

// --------- merged BN1 finalize + W1 fold/split + b1 fold (one kernel) --------
__global__ void k_fin1w1(const float* __restrict__ W1, const float* __restrict__ b1,
                         const float* __restrict__ gam, const float* __restrict__ bet,
                         int n) {
    __shared__ float sc[128], sh[128];
    int t = threadIdx.x;       // 256 threads, 128 blocks
    if (t < 128) {
        float mean = g_red[t] / (float)n;
        float var  = g_red[128 + t] / (float)n - mean * mean;
        float inv  = rsqrtf(var + 1e-5f);
        float s    = gam[t] * inv;
        sc[t] = s;
        sh[t] = bet[t] - mean * s;
        if (blockIdx.x == 0) { g_aff[t] = s; g_aff[128 + t] = sh[t]; }
    }
    __syncthreads();
    int i = blockIdx.x * 256 + t;           // 32768 W1 elements
    int k = i >> 8;
    splitw(sc[k] * W1[i], &g_w1h[i], &g_w1l[i]);
    if (blockIdx.x == 0) {                   // b1fold: 256 cols
        float s = b1[t];
        for (int kk = 0; kk < 128; kk++) s += sh[kk] * W1[kk * 256 + t];
        g_b1fold[t] = s;
    }
}

// ------------- merged BN2 finalize + apply (grid-stride float4) --------------
__global__ void k_fin2apply(float* __restrict__ out,
                            const float* __restrict__ gam, const float* __restrict__ bet,
                            int n, int total4) {
    __shared__ float sc[128], sh[128];
    int t = threadIdx.x;
    if (t < 128) {
        float mean = g_red[256 + t] / (float)n;
        float var  = g_red[384 + t] / (float)n - mean * mean;
        float inv  = rsqrtf(var + 1e-5f);
        float s    = gam[t] * inv;
        sc[t] = s;
        sh[t] = bet[t] - mean * s;
    }
    __syncthreads();
    for (int i = blockIdx.x * blockDim.x + t; i < total4; i += gridDim.x * blockDim.x) {
        float4 v = *(float4*)(out + (size_t)i * 4);
        int c = (i * 4) & 127;
        v.x = v.x * sc[c]     + sh[c];
        v.y = v.y * sc[c + 1] + sh[c + 1];
        v.z = v.z * sc[c + 2] + sh[c + 2];
        v.w = v.w * sc[c + 3] + sh[c + 3];
        *(float4*)(out + (size_t)i * 4) = v;
    }
}

// ------------------------------- launcher ------------------------------------
extern "C" void kernel_launch(void* const* d_in, const int* in_sizes, int n_in,
                              void* d_out, int out_size) {
    const float* x   = (const float*)d_in[0];
    const void*  ei  = d_in[1];
    const float* WQ  = (const float*)d_in[2];
    const float* WK  = (const float*)d_in[3];
    const float* WV  = (const float*)d_in[4];
    const float* WO  = (const float*)d_in[5];
    const float* bO  = (const float*)d_in[6];
    const float* W1  = (const float*)d_in[7];
    const float* b1  = (const float*)d_in[8];
    const float* W2  = (const float*)d_in[9];
    const float* b2  = (const float*)d_in[10];
    const float* g1v = (const float*)d_in[11];
    const float* be1 = (const float*)d_in[12];
    const float* g2v = (const float*)d_in[13];
    const float* be2 = (const float*)d_in[14];

    int n = in_sizes[0] / 128;
    int e = in_sizes[1] / 2;
    float* out = (float*)d_out;

    int nb = (n + 1023) / 1024;

    // #1: detect + zero (both streams depend on this)
    k_init<<<(n + 255) / 256, 256>>>(ei, e, n);
    cudaEventRecord(g_e1, 0);

    // main stream: x split, weight split, QKV GEMM (launches #2..#4)
    k_split_x<<<(n * 32 + 255) / 256, 256>>>(x, n * 32);
    k_prepw  <<<256, 256>>>(WQ, WK, WV, WO, W2);

    dim3 gQKV((n + 127) / 128, 3);
    dim3 g1g((n + 127) / 128, 1);
    dim3 g2g((n + 127) / 128, 2);

    pgemm<<<gQKV, 256>>>(0, 8, 384, 0, 0, -1, n, 128, 384,
                         0, -1, 0, -1, 0, 0, -1, 0, -1);

    // fork: CSR build on g_s2, overlapping split/prep/QKV on main
    cudaStreamWaitEvent(g_s2, g_e1, 0);
    k_hist   <<<(e + 255) / 256, 256, 0, g_s2>>>(ei, e);
    k_scan1  <<<nb, 1024, 0, g_s2>>>(n);
    k_scan2  <<<1, 32, 0, g_s2>>>(nb);
    k_scan3  <<<nb, 1024, 0, g_s2>>>(n, e);
    k_scatter<<<(e + 255) / 256, 256, 0, g_s2>>>(ei, e);
    cudaEventRecord(g_e2, g_s2);
    cudaStreamWaitEvent(0, g_e2, 0);

    // join: attention (needs QKV + CSR)
    k_attn<<<(n + 7) / 8, 256>>>(n);

    // h1 = agg @ WO + bO + x  (BN1 stats fused)
    pgemm<<<g1g, 256>>>(2, 10, 128, 0, 1, 4, n, 128, 128,
                        bO, -1, x, -1, 1, 128, -1, 0, 0);

    // BN1 finalize + W1 fold/split + b1 fold (one kernel)
    k_fin1w1<<<128, 256>>>(W1, b1, g1v, be1, n);

    // hidden = relu( h1 @ W1' + b1fold )
    pgemm<<<g2g, 256>>>(4, 12, 256, 0, -1, 6, n, 128, 256,
                        0, 2, 0, -1, 0, 0, -1, 1, -1);

    // out = hidden @ W2 + b2 + BN1(h1)  (BN2 stats fused)
    pgemm<<<g1g, 256>>>(6, 14, 128, out, -1, -1, n, 256, 128,
                        b2, -1, 0, 1, 1, 128, 0, 0, 2);

    // BN2 finalize + apply (one kernel)
    k_fin2apply<<<1600, 256>>>(out, g2v, be2, n, n * 32);
}